// round 8
// baseline (speedup 1.0000x reference)
#include <cuda_runtime.h>
#include <cuda_bf16.h>
#include <math.h>
#include <stdint.h>

#define HID  2048
#define NSEQ 2048
#define NH   16
#define HD   128
#define TOPK 256

// ---------------- scratch (device globals; no allocation) ----------------
__device__ float g_Q[NSEQ * HID];
__device__ float g_K[NSEQ * HID];
__device__ float g_part[16 * HID];
__device__ float g_qbar[HID];
__device__ float g_imp[NH * NSEQ];
__device__ int   g_idx[NH * TOPK];
__device__ int   g_cnt[NH];

__device__ __align__(16) __nv_bfloat16 g_Xh[NSEQ * HID];
__device__ __align__(16) __nv_bfloat16 g_Xl[NSEQ * HID];
__device__ __align__(16) __nv_bfloat16 g_Oh[NSEQ * HID];
__device__ __align__(16) __nv_bfloat16 g_Ol[NSEQ * HID];
__device__ __align__(16) __nv_bfloat16 g_Qh[NSEQ * HID];
__device__ __align__(16) __nv_bfloat16 g_Ql[NSEQ * HID];
__device__ __align__(16) __nv_bfloat16 g_Kh[NSEQ * HID];
__device__ __align__(16) __nv_bfloat16 g_Kl[NSEQ * HID];
__device__ __align__(16) __nv_bfloat16 g_Vh[NSEQ * HID];
__device__ __align__(16) __nv_bfloat16 g_Vl[NSEQ * HID];
__device__ __align__(16) __nv_bfloat16 g_Wh[4][HID * HID];   // W^T splits, [N][K]
__device__ __align__(16) __nv_bfloat16 g_Wl[4][HID * HID];

// ======================= PTX helpers (plain sm_103-safe) =======================
__device__ __forceinline__ void ldsm4(uint32_t addr, uint32_t* r) {
    asm volatile("ldmatrix.sync.aligned.m8n8.x4.shared.b16 {%0,%1,%2,%3}, [%4];"
                 : "=r"(r[0]), "=r"(r[1]), "=r"(r[2]), "=r"(r[3]) : "r"(addr));
}
__device__ __forceinline__ void ldsm4t(uint32_t addr, uint32_t* r) {
    asm volatile("ldmatrix.sync.aligned.m8n8.x4.trans.shared.b16 {%0,%1,%2,%3}, [%4];"
                 : "=r"(r[0]), "=r"(r[1]), "=r"(r[2]), "=r"(r[3]) : "r"(addr));
}
__device__ __forceinline__ void mma16816(float* d, const uint32_t* a, uint32_t b0, uint32_t b1) {
    asm volatile("mma.sync.aligned.m16n8k16.row.col.f32.bf16.bf16.f32 "
                 "{%0,%1,%2,%3}, {%4,%5,%6,%7}, {%8,%9}, {%0,%1,%2,%3};"
                 : "+f"(d[0]), "+f"(d[1]), "+f"(d[2]), "+f"(d[3])
                 : "r"(a[0]), "r"(a[1]), "r"(a[2]), "r"(a[3]), "r"(b0), "r"(b1));
}
#define CP16(dst, src) \
    asm volatile("cp.async.cg.shared.global [%0], [%1], 16;" :: "r"(dst), "l"(src))
#define CP_COMMIT() asm volatile("cp.async.commit_group;" ::: "memory")
#define CP_WAIT1()  asm volatile("cp.async.wait_group 1;" ::: "memory")
#define CP_WAIT0()  asm volatile("cp.async.wait_group 0;" ::: "memory")

__device__ __forceinline__ void split_store(__nv_bfloat16* Ch, __nv_bfloat16* Cl,
                                            int row, int col, float2 v) {
    __nv_bfloat16 h0 = __float2bfloat16(v.x), h1 = __float2bfloat16(v.y);
    uint32_t hw = (uint32_t)__bfloat16_as_ushort(h0) |
                  ((uint32_t)__bfloat16_as_ushort(h1) << 16);
    __nv_bfloat16 l0 = __float2bfloat16(v.x - __bfloat162float(h0));
    __nv_bfloat16 l1 = __float2bfloat16(v.y - __bfloat162float(h1));
    uint32_t lw = (uint32_t)__bfloat16_as_ushort(l0) |
                  ((uint32_t)__bfloat16_as_ushort(l1) << 16);
    *(uint32_t*)&Ch[(size_t)row * HID + col] = hw;
    *(uint32_t*)&Cl[(size_t)row * HID + col] = lw;
}

// ======================= split / transpose-split =======================
__global__ void split_f32(const float* __restrict__ x,
                          __nv_bfloat16* __restrict__ hi, __nv_bfloat16* __restrict__ lo) {
    int i = (blockIdx.x * 256 + threadIdx.x) * 4;
    float4 v = *(const float4*)(x + i);
    __nv_bfloat16 h0 = __float2bfloat16(v.x);
    __nv_bfloat16 h1 = __float2bfloat16(v.y);
    __nv_bfloat16 h2 = __float2bfloat16(v.z);
    __nv_bfloat16 h3 = __float2bfloat16(v.w);
    ushort4 hv = {__bfloat16_as_ushort(h0), __bfloat16_as_ushort(h1),
                  __bfloat16_as_ushort(h2), __bfloat16_as_ushort(h3)};
    __nv_bfloat16 l0 = __float2bfloat16(v.x - __bfloat162float(h0));
    __nv_bfloat16 l1 = __float2bfloat16(v.y - __bfloat162float(h1));
    __nv_bfloat16 l2 = __float2bfloat16(v.z - __bfloat162float(h2));
    __nv_bfloat16 l3 = __float2bfloat16(v.w - __bfloat162float(h3));
    ushort4 lv = {__bfloat16_as_ushort(l0), __bfloat16_as_ushort(l1),
                  __bfloat16_as_ushort(l2), __bfloat16_as_ushort(l3)};
    *(ushort4*)(hi + i) = hv;
    *(ushort4*)(lo + i) = lv;
}

// all 4 weights: [K][N] fp32 -> [N][K] bf16 hi/lo
__global__ void transpose_split4(const float* __restrict__ W0, const float* __restrict__ W1,
                                 const float* __restrict__ W2, const float* __restrict__ W3) {
    __shared__ float t[32][33];
    const float* W = blockIdx.z == 0 ? W0 : blockIdx.z == 1 ? W1 : blockIdx.z == 2 ? W2 : W3;
    __nv_bfloat16* Th = g_Wh[blockIdx.z];
    __nv_bfloat16* Tl = g_Wl[blockIdx.z];
    int n0 = blockIdx.x * 32, k0 = blockIdx.y * 32;
    int tx = threadIdx.x, ty = threadIdx.y;  // block (32, 8)
#pragma unroll
    for (int j = 0; j < 32; j += 8)
        t[ty + j][tx] = W[(size_t)(k0 + ty + j) * HID + n0 + tx];
    __syncthreads();
#pragma unroll
    for (int j = 0; j < 32; j += 8) {
        float v = t[tx][ty + j];
        __nv_bfloat16 h = __float2bfloat16(v);
        size_t o = (size_t)(n0 + ty + j) * HID + k0 + tx;
        Th[o] = h;
        Tl[o] = __float2bfloat16(v - __bfloat162float(h));
    }
}

// ======================= HMMA bf16x3 GEMM (3-stage, 512 threads) =======================
// C = (Ah+Al)[M,K] @ (Bh+Bl)^T ([N,K]) + bias. CTA 128x128, BK=64.
// 16 warps (4/SMSP), warp tile 32x32. Stage: Ah|Al|Bh|Bl (16KB each) = 64KB x 3.
#define GSMEM (3 * 65536)

__global__ __launch_bounds__(512, 1)
void gemm_bf16x3(const __nv_bfloat16* __restrict__ Ah, const __nv_bfloat16* __restrict__ Al,
                 const __nv_bfloat16* __restrict__ Bh, const __nv_bfloat16* __restrict__ Bl,
                 const float* __restrict__ bias, float* __restrict__ C,
                 __nv_bfloat16* __restrict__ Ch, __nv_bfloat16* __restrict__ Cl) {
    extern __shared__ char smem[];
    const uint32_t sb = (uint32_t)__cvta_generic_to_shared(smem);
    const int tid = threadIdx.x, lane = tid & 31, wid = tid >> 5;   // wid 0..15
    const int m0 = blockIdx.y * 128, n0 = blockIdx.x * 128;
    const int wm = (wid >> 2) * 32, wn = (wid & 3) * 32;            // warp tile 32x32

    const __nv_bfloat16* tsrc[4] = {
        Ah + (size_t)m0 * HID, Al + (size_t)m0 * HID,
        Bh + (size_t)n0 * HID, Bl + (size_t)n0 * HID};

    float d[8][4];
#pragma unroll
    for (int i = 0; i < 8; ++i) { d[i][0] = d[i][1] = d[i][2] = d[i][3] = 0.f; }

    const int grp = lane >> 3, lr = lane & 7;
    const int arow_b = wm + (grp & 1) * 8 + lr;
    const int brow_b = wn + (grp >> 1) * 8 + lr;
    const int akc_b = grp >> 1;
    const int bkc_b = grp & 1;

    // prologue: stages 0, 1
#pragma unroll
    for (int pc = 0; pc < 2; ++pc) {
        int k0 = pc * 64;
        uint32_t sbase = sb + pc * 65536;
#pragma unroll
        for (int j = 0; j < 2; ++j) {
            int id = tid + j * 512;
            int r = id >> 3, c = id & 7;
            uint32_t doff = (uint32_t)(r * 128 + ((c ^ (r & 7)) << 4));
#pragma unroll
            for (int t = 0; t < 4; ++t)
                CP16(sbase + t * 16384 + doff, tsrc[t] + (size_t)r * HID + k0 + c * 8);
        }
        CP_COMMIT();
    }

    int sComp = 0, sPref = 2;
    for (int kc = 0; kc < 32; ++kc) {
        if (kc == 31) { CP_WAIT0(); } else { CP_WAIT1(); }
        __syncthreads();
        if (kc + 2 < 32) {
            int k0 = (kc + 2) * 64;
            uint32_t sbase = sb + sPref * 65536;
#pragma unroll
            for (int j = 0; j < 2; ++j) {
                int id = tid + j * 512;
                int r = id >> 3, c = id & 7;
                uint32_t doff = (uint32_t)(r * 128 + ((c ^ (r & 7)) << 4));
#pragma unroll
                for (int t = 0; t < 4; ++t)
                    CP16(sbase + t * 16384 + doff, tsrc[t] + (size_t)r * HID + k0 + c * 8);
            }
            CP_COMMIT();
            if (++sPref == 3) sPref = 0;
        }

        const uint32_t base = sb + sComp * 65536;
        if (++sComp == 3) sComp = 0;
        const uint32_t TAh = base, TAl = base + 16384, TBh = base + 32768, TBl = base + 49152;

#pragma unroll
        for (int ks = 0; ks < 4; ++ks) {
            uint32_t aH[2][4], aL[2][4], bH[2][4], bL[2][4];
#pragma unroll
            for (int f = 0; f < 2; ++f) {
                int row = arow_b + f * 16;
                int kc8 = ks * 2 + akc_b;
                uint32_t off = (uint32_t)(row * 128 + ((kc8 ^ (row & 7)) << 4));
                ldsm4(TAh + off, aH[f]);
                ldsm4(TAl + off, aL[f]);
            }
#pragma unroll
            for (int jn = 0; jn < 2; ++jn) {
                int row = brow_b + jn * 16;
                int kc8 = ks * 2 + bkc_b;
                uint32_t off = (uint32_t)(row * 128 + ((kc8 ^ (row & 7)) << 4));
                ldsm4(TBh + off, bH[jn]);
                ldsm4(TBl + off, bL[jn]);
            }
            // product-major sweeps: 8 independent accumulators per sweep
#pragma unroll
            for (int f = 0; f < 2; ++f)
#pragma unroll
                for (int jn = 0; jn < 2; ++jn)
#pragma unroll
                    for (int sub = 0; sub < 2; ++sub)
                        mma16816(d[f * 4 + jn * 2 + sub], aH[f],
                                 bH[jn][sub * 2], bH[jn][sub * 2 + 1]);
#pragma unroll
            for (int f = 0; f < 2; ++f)
#pragma unroll
                for (int jn = 0; jn < 2; ++jn)
#pragma unroll
                    for (int sub = 0; sub < 2; ++sub)
                        mma16816(d[f * 4 + jn * 2 + sub], aH[f],
                                 bL[jn][sub * 2], bL[jn][sub * 2 + 1]);
#pragma unroll
            for (int f = 0; f < 2; ++f)
#pragma unroll
                for (int jn = 0; jn < 2; ++jn)
#pragma unroll
                    for (int sub = 0; sub < 2; ++sub)
                        mma16816(d[f * 4 + jn * 2 + sub], aL[f],
                                 bH[jn][sub * 2], bH[jn][sub * 2 + 1]);
        }
    }

    // epilogue (warp 32x32: 2 m16 groups x 4 n8 tiles)
    const int rq = lane >> 2, cq = (lane & 3) * 2;
#pragma unroll
    for (int j = 0; j < 4; ++j) {
        int col = n0 + wn + j * 8 + cq;
        float2 bb = *(const float2*)&bias[col];
#pragma unroll
        for (int f = 0; f < 2; ++f) {
            const float* dd = d[f * 4 + j];
            int row = m0 + wm + f * 16 + rq;
            float2 o0 = {dd[0] + bb.x, dd[1] + bb.y};
            float2 o1 = {dd[2] + bb.x, dd[3] + bb.y};
            if (C) {
                *(float2*)&C[(size_t)row * HID + col]       = o0;
                *(float2*)&C[(size_t)(row + 8) * HID + col] = o1;
            }
            if (Ch) {
                split_store(Ch, Cl, row, col, o0);
                split_store(Ch, Cl, row + 8, col, o1);
            }
        }
    }
}

// ---------------- column sum of Q (for qbar) ----------------
__global__ void colsum_part() {
    int c = blockIdx.x * 256 + threadIdx.x;
    int chunk = blockIdx.y;
    int n0 = chunk * 128;
    float s = 0.f;
#pragma unroll 8
    for (int n = 0; n < 128; ++n) s += g_Q[(n0 + n) * HID + c];
    g_part[chunk * HID + c] = s;
}

__global__ void colsum_final() {
    int c = blockIdx.x * 256 + threadIdx.x;
    float s = 0.f;
#pragma unroll
    for (int t = 0; t < 16; ++t) s += g_part[t * HID + c];
    g_qbar[c] = s;
}

// ---------------- importance[h, m] = qbar_h . k_m ----------------
__global__ void imp_kernel() {
    if (blockIdx.x == 0 && threadIdx.x < NH) g_cnt[threadIdx.x] = 0;
    int gw = (blockIdx.x * blockDim.x + threadIdx.x) >> 5;
    int lane = threadIdx.x & 31;
    int h = gw >> 11, m = gw & 2047;
    float4 kv = *(const float4*)&g_K[(size_t)m * HID + h * HD + lane * 4];
    float4 qv = *(const float4*)&g_qbar[h * HD + lane * 4];
    float s = kv.x * qv.x + kv.y * qv.y + kv.z * qv.z + kv.w * qv.w;
#pragma unroll
    for (int o = 16; o; o >>= 1) s += __shfl_xor_sync(0xffffffffu, s, o);
    if (!lane) g_imp[h * NSEQ + m] = s;
}

// ---------------- top-k by rank counting (64 blocks: 4 segments/head) ----------------
__global__ void topk_kernel() {
    __shared__ float sv[NSEQ];
    int h = blockIdx.x >> 2, seg = blockIdx.x & 3, tid = threadIdx.x;
    for (int i = tid; i < NSEQ; i += 256) sv[i] = g_imp[h * NSEQ + i];
    __syncthreads();
    const float4* p4 = (const float4*)sv;
#pragma unroll
    for (int e = 0; e < 2; ++e) {
        int m = seg * 512 + e * 256 + tid;
        float v = sv[m];
        int rank = 0;
        for (int j4 = 0; j4 < NSEQ / 4; ++j4) {
            float4 x = p4[j4];
            int jb = j4 * 4;
            rank += (x.x > v) + (x.y > v) + (x.z > v) + (x.w > v);
            rank += (x.x == v && jb + 0 < m);
            rank += (x.y == v && jb + 1 < m);
            rank += (x.z == v && jb + 2 < m);
            rank += (x.w == v && jb + 3 < m);
        }
        if (rank < TOPK) {
            int pos = atomicAdd(&g_cnt[h], 1);
            g_idx[h * TOPK + pos] = m;
        }
    }
}

// ======================= HMMA bf16x3 sparse attention =======================
#define AT_QH   0
#define AT_QL   16384
#define AT_KST  32768
#define AT_S    98304
#define AT_IDX  163840
#define ATTN_SMEM (163840 + 1024)

__device__ __forceinline__ void gather_kv(uint32_t dstStage,
                                          const __nv_bfloat16* __restrict__ Hi,
                                          const __nv_bfloat16* __restrict__ Lo,
                                          const int* sidx, int kc, int tid, int HB) {
#pragma unroll
    for (int j = 0; j < 4; ++j) {
        int id = tid + j * 256;
        int r = id >> 4, c = id & 15;
        int key = sidx[kc * 64 + r];
        uint32_t dst = dstStage + (uint32_t)(r * 256 + ((c ^ (r & 7)) << 4));
        CP16(dst,         Hi + (size_t)key * HID + HB + c * 8);
        CP16(dst + 16384, Lo + (size_t)key * HID + HB + c * 8);
    }
}

__global__ __launch_bounds__(256, 1)
void attn_mma() {
    extern __shared__ char smc[];
    const uint32_t sb = (uint32_t)__cvta_generic_to_shared(smc);
    const int tid = threadIdx.x, lane = tid & 31, wid = tid >> 5;
    const int h = blockIdx.y, n0 = blockIdx.x * 64, HB = h * HD;
    const int grp = lane >> 3, lr = lane & 7;
    const int fm = wid >> 1;
    const int rq = lane >> 2, cq = (lane & 3) * 2;
    const float SCALE = 0.08838834764831845f;

    int* sidx = (int*)(smc + AT_IDX);
    sidx[tid] = g_idx[h * TOPK + tid];
    __syncthreads();

#pragma unroll
    for (int j = 0; j < 4; ++j) {
        int id = tid + j * 256;
        int r = id >> 4, c = id & 15;
        uint32_t dst = sb + AT_QH + (uint32_t)(r * 256 + ((c ^ (r & 7)) << 4));
        CP16(dst,         g_Qh + (size_t)(n0 + r) * HID + HB + c * 8);
        CP16(dst + 16384, g_Ql + (size_t)(n0 + r) * HID + HB + c * 8);
    }
    gather_kv(sb + AT_KST, g_Kh, g_Kl, sidx, 0, tid, HB);
    CP_COMMIT();

    // ---- phase 1: S = scale * (QhKh + QhKl + QlKh)^T over 4 key chunks ----
    const int wn1 = (wid & 1) * 32;
    float* Sf = (float*)(smc + AT_S);
    for (int kc = 0; kc < 4; ++kc) {
        CP_WAIT0();
        __syncthreads();
        if (kc + 1 < 4) {
            gather_kv(sb + AT_KST + ((kc + 1) & 1) * 32768, g_Kh, g_Kl, sidx, kc + 1, tid, HB);
            CP_COMMIT();
        }
        const uint32_t KH = sb + AT_KST + (kc & 1) * 32768, KL = KH + 16384;
        const uint32_t QH = sb + AT_QH, QL = sb + AT_QL;
        float acc[4][4] = {};
        const int arow = fm * 16 + (grp & 1) * 8 + lr;
        const int brow = wn1 + (grp >> 1) * 8 + lr;
#pragma unroll
        for (int ks = 0; ks < 8; ++ks) {
            uint32_t aH[4], aL[4], bH[2][4], bL[2][4];
            {
                int ca = ks * 2 + (grp >> 1);
                uint32_t off = (uint32_t)(arow * 256 + ((ca ^ (arow & 7)) << 4));
                ldsm4(QH + off, aH);
                ldsm4(QL + off, aL);
            }
            {
                int cb = ks * 2 + (grp & 1);
#pragma unroll
                for (int hf = 0; hf < 2; ++hf) {
                    int row = brow + hf * 16;
                    uint32_t off = (uint32_t)(row * 256 + ((cb ^ (row & 7)) << 4));
                    ldsm4(KH + off, bH[hf]);
                    ldsm4(KL + off, bL[hf]);
                }
            }
#pragma unroll
            for (int hf = 0; hf < 2; ++hf)
#pragma unroll
                for (int sub = 0; sub < 2; ++sub)
                    mma16816(acc[hf * 2 + sub], aH, bH[hf][sub * 2], bH[hf][sub * 2 + 1]);
#pragma unroll
            for (int hf = 0; hf < 2; ++hf)
#pragma unroll
                for (int sub = 0; sub < 2; ++sub)
                    mma16816(acc[hf * 2 + sub], aH, bL[hf][sub * 2], bL[hf][sub * 2 + 1]);
#pragma unroll
            for (int hf = 0; hf < 2; ++hf)
#pragma unroll
                for (int sub = 0; sub < 2; ++sub)
                    mma16816(acc[hf * 2 + sub], aL, bH[hf][sub * 2], bH[hf][sub * 2 + 1]);
        }
#pragma unroll
        for (int jf = 0; jf < 4; ++jf) {
            int col = kc * 64 + wn1 + jf * 8 + cq;
            float2 v0 = {acc[jf][0] * SCALE, acc[jf][1] * SCALE};
            float2 v1 = {acc[jf][2] * SCALE, acc[jf][3] * SCALE};
            *(float2*)&Sf[(fm * 16 + rq) * 256 + col]     = v0;
            *(float2*)&Sf[(fm * 16 + rq + 8) * 256 + col] = v1;
        }
    }
    __syncthreads();

    gather_kv(sb + AT_KST, g_Vh, g_Vl, sidx, 0, tid, HB);
    CP_COMMIT();

    // ---- phase 2: softmax, pack weights into Wh/Wl ----
    {
        for (int r = wid; r < 64; r += 8) {
            float vals[8], mx = -1e30f;
            float* Sr = (float*)(smc + AT_S + r * 1024);
#pragma unroll
            for (int t = 0; t < 8; ++t) {
                vals[t] = Sr[lane + t * 32];
                mx = fmaxf(mx, vals[t]);
            }
#pragma unroll
            for (int o = 16; o; o >>= 1) mx = fmaxf(mx, __shfl_xor_sync(0xffffffffu, mx, o));
            float ssum = 0.f;
#pragma unroll
            for (int t = 0; t < 8; ++t) { vals[t] = expf(vals[t] - mx); ssum += vals[t]; }
#pragma unroll
            for (int o = 16; o; o >>= 1) ssum += __shfl_xor_sync(0xffffffffu, ssum, o);
            float inv = 1.0f / ssum;
            char* rowb = smc + AT_S + r * 1024;
#pragma unroll
            for (int t = 0; t < 8; ++t) {
                float w = vals[t] * inv;
                __nv_bfloat16 hi = __float2bfloat16(w);
                __nv_bfloat16 lo = __float2bfloat16(w - __bfloat162float(hi));
                int key = lane + t * 32;
                int c = key >> 3, wi = key & 7;
                int swz = ((c ^ (r & 7)) << 4) + wi * 2;
                *(__nv_bfloat16*)(rowb + swz)       = hi;
                *(__nv_bfloat16*)(rowb + 512 + swz) = lo;
            }
        }
    }

    // ---- phase 3: O = (WhVh + WhVl + WlVh) over 4 key chunks ----
    float oacc[8][4];
#pragma unroll
    for (int i = 0; i < 8; ++i) { oacc[i][0] = oacc[i][1] = oacc[i][2] = oacc[i][3] = 0.f; }
    const int wn3 = (wid & 1) * 64;
    for (int kc = 0; kc < 4; ++kc) {
        CP_WAIT0();
        __syncthreads();
        if (kc + 1 < 4) {
            gather_kv(sb + AT_KST + ((kc + 1) & 1) * 32768, g_Vh, g_Vl, sidx, kc + 1, tid, HB);
            CP_COMMIT();
        }
        const uint32_t VH = sb + AT_KST + (kc & 1) * 32768, VL = VH + 16384;
#pragma unroll
        for (int ks = 0; ks < 4; ++ks) {
            uint32_t aH[4], aL[4];
            {
                int cg = kc * 8 + ks * 2 + (grp >> 1);
                int arow = fm * 16 + (grp & 1) * 8 + lr;
                uint32_t off = (uint32_t)(arow * 1024 + ((cg ^ (arow & 7)) << 4));
                ldsm4(sb + AT_S + off, aH);
                ldsm4(sb + AT_S + off + 512, aL);
            }
            uint32_t bH[4][4], bL[4][4];
            {
                int vrow = ks * 16 + (grp & 1) * 8 + lr;
                uint32_t rbase = (uint32_t)(vrow * 256);
                int cbase = (wn3 >> 3) + (grp >> 1);
#pragma unroll
                for (int g4 = 0; g4 < 4; ++g4) {
                    int cn = cbase + g4 * 2;
                    uint32_t off = rbase + ((cn ^ (vrow & 7)) << 4);
                    ldsm4t(VH + off, bH[g4]);
                    ldsm4t(VL + off, bL[g4]);
                }
            }
#pragma unroll
            for (int g4 = 0; g4 < 4; ++g4)
#pragma unroll
                for (int s2 = 0; s2 < 2; ++s2)
                    mma16816(oacc[g4 * 2 + s2], aH, bH[g4][s2 * 2], bH[g4][s2 * 2 + 1]);
#pragma unroll
            for (int g4 = 0; g4 < 4; ++g4)
#pragma unroll
                for (int s2 = 0; s2 < 2; ++s2)
                    mma16816(oacc[g4 * 2 + s2], aH, bL[g4][s2 * 2], bL[g4][s2 * 2 + 1]);
#pragma unroll
            for (int g4 = 0; g4 < 4; ++g4)
#pragma unroll
                for (int s2 = 0; s2 < 2; ++s2)
                    mma16816(oacc[g4 * 2 + s2], aL, bH[g4][s2 * 2], bH[g4][s2 * 2 + 1]);
        }
    }

    // epilogue: split O into Oh/Ol directly
#pragma unroll
    for (int j = 0; j < 8; ++j) {
        int col = HB + wn3 + j * 8 + cq;
        int row = n0 + fm * 16 + rq;
        float2 v0 = {oacc[j][0], oacc[j][1]};
        float2 v1 = {oacc[j][2], oacc[j][3]};
        split_store(g_Oh, g_Ol, row, col, v0);
        split_store(g_Oh, g_Ol, row + 8, col, v1);
    }
}

// ======================= host =======================
extern "C" void kernel_launch(void* const* d_in, const int* in_sizes, int n_in,
                              void* d_out, int out_size) {
    const float* X  = (const float*)d_in[0];
    const float* Wq = (const float*)d_in[1];
    const float* bq = (const float*)d_in[2];
    const float* Wk = (const float*)d_in[3];
    const float* bk = (const float*)d_in[4];
    const float* Wv = (const float*)d_in[5];
    const float* bv = (const float*)d_in[6];
    const float* Wo = (const float*)d_in[7];
    const float* bo = (const float*)d_in[8];
    float* out = (float*)d_out;

    float *Qd, *Kd;
    __nv_bfloat16 *Xh, *Xl, *Oh, *Ol, *Wh, *Wl, *Qh, *Ql, *Kh, *Kl, *Vh, *Vl;
    cudaGetSymbolAddress((void**)&Qd, g_Q);
    cudaGetSymbolAddress((void**)&Kd, g_K);
    cudaGetSymbolAddress((void**)&Xh, g_Xh);
    cudaGetSymbolAddress((void**)&Xl, g_Xl);
    cudaGetSymbolAddress((void**)&Oh, g_Oh);
    cudaGetSymbolAddress((void**)&Ol, g_Ol);
    cudaGetSymbolAddress((void**)&Wh, g_Wh);
    cudaGetSymbolAddress((void**)&Wl, g_Wl);
    cudaGetSymbolAddress((void**)&Qh, g_Qh);
    cudaGetSymbolAddress((void**)&Ql, g_Ql);
    cudaGetSymbolAddress((void**)&Kh, g_Kh);
    cudaGetSymbolAddress((void**)&Kl, g_Kl);
    cudaGetSymbolAddress((void**)&Vh, g_Vh);
    cudaGetSymbolAddress((void**)&Vl, g_Vl);

    cudaFuncSetAttribute(gemm_bf16x3, cudaFuncAttributeMaxDynamicSharedMemorySize, GSMEM);
    cudaFuncSetAttribute(attn_mma, cudaFuncAttributeMaxDynamicSharedMemorySize, ATTN_SMEM);

    const size_t WSZ = (size_t)HID * HID;

    split_f32<<<4096, 256>>>(X, Xh, Xl);
    transpose_split4<<<dim3(64, 64, 4), dim3(32, 8)>>>(Wq, Wk, Wv, Wo);

    dim3 gg(16, 16);
    gemm_bf16x3<<<gg, 512, GSMEM>>>(Xh, Xl, Wh + 0 * WSZ, Wl + 0 * WSZ, bq, Qd, Qh, Ql);
    gemm_bf16x3<<<gg, 512, GSMEM>>>(Xh, Xl, Wh + 1 * WSZ, Wl + 1 * WSZ, bk, Kd, Kh, Kl);
    gemm_bf16x3<<<gg, 512, GSMEM>>>(Xh, Xl, Wh + 2 * WSZ, Wl + 2 * WSZ, bv, nullptr, Vh, Vl);

    colsum_part<<<dim3(8, 16), 256>>>();
    colsum_final<<<8, 256>>>();
    imp_kernel<<<4096, 256>>>();
    topk_kernel<<<64, 256>>>();

    attn_mma<<<dim3(32, 16), 256, ATTN_SMEM>>>();

    gemm_bf16x3<<<gg, 512, GSMEM>>>(Oh, Ol, Wh + 3 * WSZ, Wl + 3 * WSZ, bo, out,
                                    nullptr, nullptr);
}

// round 9
// speedup vs baseline: 1.0635x; 1.0635x over previous
#include <cuda_runtime.h>
#include <cuda_bf16.h>
#include <math.h>
#include <stdint.h>

#define HID  2048
#define NSEQ 2048
#define NH   16
#define HD   128
#define TOPK 256

// ---------------- scratch (device globals; no allocation) ----------------
__device__ float g_Q[NSEQ * HID];
__device__ float g_K[NSEQ * HID];
__device__ float g_part[16 * HID];
__device__ float g_qbar[HID];
__device__ float g_imp[NH * NSEQ];
__device__ int   g_idx[NH * TOPK];
__device__ int   g_cnt[NH];

__device__ __align__(16) __nv_bfloat16 g_Xh[NSEQ * HID];
__device__ __align__(16) __nv_bfloat16 g_Xl[NSEQ * HID];
__device__ __align__(16) __nv_bfloat16 g_Oh[NSEQ * HID];
__device__ __align__(16) __nv_bfloat16 g_Ol[NSEQ * HID];
__device__ __align__(16) __nv_bfloat16 g_Qh[NSEQ * HID];
__device__ __align__(16) __nv_bfloat16 g_Ql[NSEQ * HID];
__device__ __align__(16) __nv_bfloat16 g_Kh[NSEQ * HID];
__device__ __align__(16) __nv_bfloat16 g_Kl[NSEQ * HID];
__device__ __align__(16) __nv_bfloat16 g_Vh[NSEQ * HID];
__device__ __align__(16) __nv_bfloat16 g_Vl[NSEQ * HID];
__device__ __align__(16) __nv_bfloat16 g_Wh[4][HID * HID];   // W^T splits, [N][K]
__device__ __align__(16) __nv_bfloat16 g_Wl[4][HID * HID];

// ======================= PTX helpers (plain sm_103-safe) =======================
__device__ __forceinline__ void ldsm4(uint32_t addr, uint32_t* r) {
    asm volatile("ldmatrix.sync.aligned.m8n8.x4.shared.b16 {%0,%1,%2,%3}, [%4];"
                 : "=r"(r[0]), "=r"(r[1]), "=r"(r[2]), "=r"(r[3]) : "r"(addr));
}
__device__ __forceinline__ void ldsm4t(uint32_t addr, uint32_t* r) {
    asm volatile("ldmatrix.sync.aligned.m8n8.x4.trans.shared.b16 {%0,%1,%2,%3}, [%4];"
                 : "=r"(r[0]), "=r"(r[1]), "=r"(r[2]), "=r"(r[3]) : "r"(addr));
}
__device__ __forceinline__ void mma16816(float* d, const uint32_t* a, uint32_t b0, uint32_t b1) {
    asm volatile("mma.sync.aligned.m16n8k16.row.col.f32.bf16.bf16.f32 "
                 "{%0,%1,%2,%3}, {%4,%5,%6,%7}, {%8,%9}, {%0,%1,%2,%3};"
                 : "+f"(d[0]), "+f"(d[1]), "+f"(d[2]), "+f"(d[3])
                 : "r"(a[0]), "r"(a[1]), "r"(a[2]), "r"(a[3]), "r"(b0), "r"(b1));
}
#define CP16(dst, src) \
    asm volatile("cp.async.cg.shared.global [%0], [%1], 16;" :: "r"(dst), "l"(src))
#define CP_COMMIT() asm volatile("cp.async.commit_group;" ::: "memory")
#define CP_WAIT1()  asm volatile("cp.async.wait_group 1;" ::: "memory")
#define CP_WAIT0()  asm volatile("cp.async.wait_group 0;" ::: "memory")

__device__ __forceinline__ void split_store(__nv_bfloat16* Ch, __nv_bfloat16* Cl,
                                            int row, int col, float2 v) {
    __nv_bfloat16 h0 = __float2bfloat16(v.x), h1 = __float2bfloat16(v.y);
    uint32_t hw = (uint32_t)__bfloat16_as_ushort(h0) |
                  ((uint32_t)__bfloat16_as_ushort(h1) << 16);
    __nv_bfloat16 l0 = __float2bfloat16(v.x - __bfloat162float(h0));
    __nv_bfloat16 l1 = __float2bfloat16(v.y - __bfloat162float(h1));
    uint32_t lw = (uint32_t)__bfloat16_as_ushort(l0) |
                  ((uint32_t)__bfloat16_as_ushort(l1) << 16);
    *(uint32_t*)&Ch[(size_t)row * HID + col] = hw;
    *(uint32_t*)&Cl[(size_t)row * HID + col] = lw;
}

// ======================= split / transpose-split =======================
__global__ void split_f32(const float* __restrict__ x,
                          __nv_bfloat16* __restrict__ hi, __nv_bfloat16* __restrict__ lo) {
    int i = (blockIdx.x * 256 + threadIdx.x) * 4;
    float4 v = *(const float4*)(x + i);
    __nv_bfloat16 h0 = __float2bfloat16(v.x);
    __nv_bfloat16 h1 = __float2bfloat16(v.y);
    __nv_bfloat16 h2 = __float2bfloat16(v.z);
    __nv_bfloat16 h3 = __float2bfloat16(v.w);
    ushort4 hv = {__bfloat16_as_ushort(h0), __bfloat16_as_ushort(h1),
                  __bfloat16_as_ushort(h2), __bfloat16_as_ushort(h3)};
    __nv_bfloat16 l0 = __float2bfloat16(v.x - __bfloat162float(h0));
    __nv_bfloat16 l1 = __float2bfloat16(v.y - __bfloat162float(h1));
    __nv_bfloat16 l2 = __float2bfloat16(v.z - __bfloat162float(h2));
    __nv_bfloat16 l3 = __float2bfloat16(v.w - __bfloat162float(h3));
    ushort4 lv = {__bfloat16_as_ushort(l0), __bfloat16_as_ushort(l1),
                  __bfloat16_as_ushort(l2), __bfloat16_as_ushort(l3)};
    *(ushort4*)(hi + i) = hv;
    *(ushort4*)(lo + i) = lv;
}

// all 4 weights: [K][N] fp32 -> [N][K] bf16 hi/lo
__global__ void transpose_split4(const float* __restrict__ W0, const float* __restrict__ W1,
                                 const float* __restrict__ W2, const float* __restrict__ W3) {
    __shared__ float t[32][33];
    const float* W = blockIdx.z == 0 ? W0 : blockIdx.z == 1 ? W1 : blockIdx.z == 2 ? W2 : W3;
    __nv_bfloat16* Th = g_Wh[blockIdx.z];
    __nv_bfloat16* Tl = g_Wl[blockIdx.z];
    int n0 = blockIdx.x * 32, k0 = blockIdx.y * 32;
    int tx = threadIdx.x, ty = threadIdx.y;  // block (32, 8)
#pragma unroll
    for (int j = 0; j < 32; j += 8)
        t[ty + j][tx] = W[(size_t)(k0 + ty + j) * HID + n0 + tx];
    __syncthreads();
#pragma unroll
    for (int j = 0; j < 32; j += 8) {
        float v = t[tx][ty + j];
        __nv_bfloat16 h = __float2bfloat16(v);
        size_t o = (size_t)(n0 + ty + j) * HID + k0 + tx;
        Th[o] = h;
        Tl[o] = __float2bfloat16(v - __bfloat162float(h));
    }
}

// ======================= HMMA bf16x3 GEMM =======================
// C = (Ah+Al)[M,K] @ (Bh+Bl)^T ([N,K]) + bias.
// CTA 128x256, BK=64, 8 warps, warp tile 64x64 (2x4 warp grid). Single wave (128 CTAs).
// Stage: Ah(16K)|Al(16K)|Bh(32K)|Bl(32K) = 96KB; 2 stages = 192KB.
#define OFF_AL 16384
#define OFF_BH 32768
#define OFF_BL 65536
#define GSTAGE 98304
#define GSMEM  (2 * GSTAGE)

__global__ __launch_bounds__(256, 1)
void gemm_bf16x3(const __nv_bfloat16* __restrict__ Ah, const __nv_bfloat16* __restrict__ Al,
                 const __nv_bfloat16* __restrict__ Bh, const __nv_bfloat16* __restrict__ Bl,
                 const float* __restrict__ bias, float* __restrict__ C,
                 __nv_bfloat16* __restrict__ Ch, __nv_bfloat16* __restrict__ Cl) {
    extern __shared__ char smem[];
    const uint32_t sb = (uint32_t)__cvta_generic_to_shared(smem);
    const int tid = threadIdx.x, lane = tid & 31, wid = tid >> 5;
    const int m0 = blockIdx.y * 128, n0 = blockIdx.x * 256;
    const int wm = (wid >> 2) * 64, wn = (wid & 3) * 64;   // warp tile 64x64

    const __nv_bfloat16* pAh = Ah + (size_t)m0 * HID;
    const __nv_bfloat16* pAl = Al + (size_t)m0 * HID;
    const __nv_bfloat16* pBh = Bh + (size_t)n0 * HID;
    const __nv_bfloat16* pBl = Bl + (size_t)n0 * HID;

    float d[32][4];
#pragma unroll
    for (int i = 0; i < 32; ++i) { d[i][0] = d[i][1] = d[i][2] = d[i][3] = 0.f; }

    const int grp = lane >> 3, lr = lane & 7;
    const int arow_b = wm + (grp & 1) * 8 + lr;
    const int brow_b = wn + (grp >> 1) * 8 + lr;
    const int akc_b = grp >> 1;
    const int bkc_b = grp & 1;

    // stage loader: A 128x64 (h+l), B 256x64 (h+l)
    auto load_stage = [&](int stage, int k0) {
        uint32_t sbase = sb + stage * GSTAGE;
#pragma unroll
        for (int j = 0; j < 4; ++j) {          // A: 1024 16B chunks per tile
            int id = tid + j * 256;
            int r = id >> 3, c = id & 7;
            uint32_t doff = (uint32_t)(r * 128 + ((c ^ (r & 7)) << 4));
            CP16(sbase + doff,          pAh + (size_t)r * HID + k0 + c * 8);
            CP16(sbase + OFF_AL + doff, pAl + (size_t)r * HID + k0 + c * 8);
        }
#pragma unroll
        for (int j = 0; j < 8; ++j) {          // B: 2048 16B chunks per tile
            int id = tid + j * 256;
            int r = id >> 3, c = id & 7;
            uint32_t doff = (uint32_t)(r * 128 + ((c ^ (r & 7)) << 4));
            CP16(sbase + OFF_BH + doff, pBh + (size_t)r * HID + k0 + c * 8);
            CP16(sbase + OFF_BL + doff, pBl + (size_t)r * HID + k0 + c * 8);
        }
        CP_COMMIT();
    };

    load_stage(0, 0);

    for (int kc = 0; kc < 32; ++kc) {
        if (kc + 1 < 32) load_stage((kc + 1) & 1, (kc + 1) * 64);
        if (kc + 1 < 32) { CP_WAIT1(); } else { CP_WAIT0(); }
        __syncthreads();

        const uint32_t base = sb + (kc & 1) * GSTAGE;
        const uint32_t TAh = base, TAl = base + OFF_AL;
        const uint32_t TBh = base + OFF_BH, TBl = base + OFF_BL;

#pragma unroll
        for (int ks = 0; ks < 4; ++ks) {
            uint32_t aH[4][4], bH[4][4];
            {
                int kc8 = ks * 2 + akc_b;
#pragma unroll
                for (int f = 0; f < 4; ++f) {
                    int row = arow_b + f * 16;
                    ldsm4(TAh + (uint32_t)(row * 128 + ((kc8 ^ (row & 7)) << 4)), aH[f]);
                }
            }
            {
                int kc8 = ks * 2 + bkc_b;
#pragma unroll
                for (int jn = 0; jn < 4; ++jn) {
                    int row = brow_b + jn * 16;
                    ldsm4(TBh + (uint32_t)(row * 128 + ((kc8 ^ (row & 7)) << 4)), bH[jn]);
                }
            }
            // sweep 1: Ah * Bh (32 independent accumulators)
#pragma unroll
            for (int f = 0; f < 4; ++f)
#pragma unroll
                for (int jn = 0; jn < 4; ++jn)
#pragma unroll
                    for (int sub = 0; sub < 2; ++sub)
                        mma16816(d[f * 8 + jn * 2 + sub], aH[f],
                                 bH[jn][sub * 2], bH[jn][sub * 2 + 1]);
            // sweep 2: Ah * Bl
            {
                uint32_t bL[4][4];
                int kc8 = ks * 2 + bkc_b;
#pragma unroll
                for (int jn = 0; jn < 4; ++jn) {
                    int row = brow_b + jn * 16;
                    ldsm4(TBl + (uint32_t)(row * 128 + ((kc8 ^ (row & 7)) << 4)), bL[jn]);
                }
#pragma unroll
                for (int f = 0; f < 4; ++f)
#pragma unroll
                    for (int jn = 0; jn < 4; ++jn)
#pragma unroll
                        for (int sub = 0; sub < 2; ++sub)
                            mma16816(d[f * 8 + jn * 2 + sub], aH[f],
                                     bL[jn][sub * 2], bL[jn][sub * 2 + 1]);
            }
            // sweep 3: Al * Bh
            {
                uint32_t aL[4][4];
                int kc8 = ks * 2 + akc_b;
#pragma unroll
                for (int f = 0; f < 4; ++f) {
                    int row = arow_b + f * 16;
                    ldsm4(TAl + (uint32_t)(row * 128 + ((kc8 ^ (row & 7)) << 4)), aL[f]);
                }
#pragma unroll
                for (int f = 0; f < 4; ++f)
#pragma unroll
                    for (int jn = 0; jn < 4; ++jn)
#pragma unroll
                        for (int sub = 0; sub < 2; ++sub)
                            mma16816(d[f * 8 + jn * 2 + sub], aL[f],
                                     bH[jn][sub * 2], bH[jn][sub * 2 + 1]);
            }
        }
        __syncthreads();
    }

    // epilogue: warp 64x64 = 4 m16 groups x 8 n8 tiles
    const int rq = lane >> 2, cq = (lane & 3) * 2;
#pragma unroll
    for (int j = 0; j < 8; ++j) {
        int col = n0 + wn + j * 8 + cq;
        float2 bb = *(const float2*)&bias[col];
#pragma unroll
        for (int f = 0; f < 4; ++f) {
            const float* dd = d[f * 8 + j];
            int row = m0 + wm + f * 16 + rq;
            float2 o0 = {dd[0] + bb.x, dd[1] + bb.y};
            float2 o1 = {dd[2] + bb.x, dd[3] + bb.y};
            if (C) {
                *(float2*)&C[(size_t)row * HID + col]       = o0;
                *(float2*)&C[(size_t)(row + 8) * HID + col] = o1;
            }
            if (Ch) {
                split_store(Ch, Cl, row, col, o0);
                split_store(Ch, Cl, row + 8, col, o1);
            }
        }
    }
}

// ---------------- column sum of Q (for qbar) ----------------
__global__ void colsum_part() {
    int c = blockIdx.x * 256 + threadIdx.x;
    int chunk = blockIdx.y;
    int n0 = chunk * 128;
    float s = 0.f;
#pragma unroll 8
    for (int n = 0; n < 128; ++n) s += g_Q[(n0 + n) * HID + c];
    g_part[chunk * HID + c] = s;
}

__global__ void colsum_final() {
    int c = blockIdx.x * 256 + threadIdx.x;
    float s = 0.f;
#pragma unroll
    for (int t = 0; t < 16; ++t) s += g_part[t * HID + c];
    g_qbar[c] = s;
}

// ---------------- importance[h, m] = qbar_h . k_m ----------------
__global__ void imp_kernel() {
    if (blockIdx.x == 0 && threadIdx.x < NH) g_cnt[threadIdx.x] = 0;
    int gw = (blockIdx.x * blockDim.x + threadIdx.x) >> 5;
    int lane = threadIdx.x & 31;
    int h = gw >> 11, m = gw & 2047;
    float4 kv = *(const float4*)&g_K[(size_t)m * HID + h * HD + lane * 4];
    float4 qv = *(const float4*)&g_qbar[h * HD + lane * 4];
    float s = kv.x * qv.x + kv.y * qv.y + kv.z * qv.z + kv.w * qv.w;
#pragma unroll
    for (int o = 16; o; o >>= 1) s += __shfl_xor_sync(0xffffffffu, s, o);
    if (!lane) g_imp[h * NSEQ + m] = s;
}

// ---------------- top-k by rank counting (64 blocks: 4 segments/head) ----------------
__global__ void topk_kernel() {
    __shared__ float sv[NSEQ];
    int h = blockIdx.x >> 2, seg = blockIdx.x & 3, tid = threadIdx.x;
    for (int i = tid; i < NSEQ; i += 256) sv[i] = g_imp[h * NSEQ + i];
    __syncthreads();
    const float4* p4 = (const float4*)sv;
#pragma unroll
    for (int e = 0; e < 2; ++e) {
        int m = seg * 512 + e * 256 + tid;
        float v = sv[m];
        int rank = 0;
        for (int j4 = 0; j4 < NSEQ / 4; ++j4) {
            float4 x = p4[j4];
            int jb = j4 * 4;
            rank += (x.x > v) + (x.y > v) + (x.z > v) + (x.w > v);
            rank += (x.x == v && jb + 0 < m);
            rank += (x.y == v && jb + 1 < m);
            rank += (x.z == v && jb + 2 < m);
            rank += (x.w == v && jb + 3 < m);
        }
        if (rank < TOPK) {
            int pos = atomicAdd(&g_cnt[h], 1);
            g_idx[h * TOPK + pos] = m;
        }
    }
}

// ======================= HMMA bf16x3 sparse attention =======================
#define AT_QH   0
#define AT_QL   16384
#define AT_KST  32768
#define AT_S    98304
#define AT_IDX  163840
#define ATTN_SMEM (163840 + 1024)

__device__ __forceinline__ void gather_kv(uint32_t dstStage,
                                          const __nv_bfloat16* __restrict__ Hi,
                                          const __nv_bfloat16* __restrict__ Lo,
                                          const int* sidx, int kc, int tid, int HB) {
#pragma unroll
    for (int j = 0; j < 4; ++j) {
        int id = tid + j * 256;
        int r = id >> 4, c = id & 15;
        int key = sidx[kc * 64 + r];
        uint32_t dst = dstStage + (uint32_t)(r * 256 + ((c ^ (r & 7)) << 4));
        CP16(dst,         Hi + (size_t)key * HID + HB + c * 8);
        CP16(dst + 16384, Lo + (size_t)key * HID + HB + c * 8);
    }
}

__global__ __launch_bounds__(256, 1)
void attn_mma() {
    extern __shared__ char smc[];
    const uint32_t sb = (uint32_t)__cvta_generic_to_shared(smc);
    const int tid = threadIdx.x, lane = tid & 31, wid = tid >> 5;
    const int h = blockIdx.y, n0 = blockIdx.x * 64, HB = h * HD;
    const int grp = lane >> 3, lr = lane & 7;
    const int fm = wid >> 1;
    const int rq = lane >> 2, cq = (lane & 3) * 2;
    const float SCALE = 0.08838834764831845f;

    int* sidx = (int*)(smc + AT_IDX);
    sidx[tid] = g_idx[h * TOPK + tid];
    __syncthreads();

#pragma unroll
    for (int j = 0; j < 4; ++j) {
        int id = tid + j * 256;
        int r = id >> 4, c = id & 15;
        uint32_t dst = sb + AT_QH + (uint32_t)(r * 256 + ((c ^ (r & 7)) << 4));
        CP16(dst,         g_Qh + (size_t)(n0 + r) * HID + HB + c * 8);
        CP16(dst + 16384, g_Ql + (size_t)(n0 + r) * HID + HB + c * 8);
    }
    gather_kv(sb + AT_KST, g_Kh, g_Kl, sidx, 0, tid, HB);
    CP_COMMIT();

    // ---- phase 1: S = scale * (QhKh + QhKl + QlKh)^T over 4 key chunks ----
    const int wn1 = (wid & 1) * 32;
    float* Sf = (float*)(smc + AT_S);
    for (int kc = 0; kc < 4; ++kc) {
        CP_WAIT0();
        __syncthreads();
        if (kc + 1 < 4) {
            gather_kv(sb + AT_KST + ((kc + 1) & 1) * 32768, g_Kh, g_Kl, sidx, kc + 1, tid, HB);
            CP_COMMIT();
        }
        const uint32_t KH = sb + AT_KST + (kc & 1) * 32768, KL = KH + 16384;
        const uint32_t QH = sb + AT_QH, QL = sb + AT_QL;
        float acc[4][4] = {};
        const int arow = fm * 16 + (grp & 1) * 8 + lr;
        const int brow = wn1 + (grp >> 1) * 8 + lr;
#pragma unroll
        for (int ks = 0; ks < 8; ++ks) {
            uint32_t aH[4], aL[4], bH[2][4], bL[2][4];
            {
                int ca = ks * 2 + (grp >> 1);
                uint32_t off = (uint32_t)(arow * 256 + ((ca ^ (arow & 7)) << 4));
                ldsm4(QH + off, aH);
                ldsm4(QL + off, aL);
            }
            {
                int cb = ks * 2 + (grp & 1);
#pragma unroll
                for (int hf = 0; hf < 2; ++hf) {
                    int row = brow + hf * 16;
                    uint32_t off = (uint32_t)(row * 256 + ((cb ^ (row & 7)) << 4));
                    ldsm4(KH + off, bH[hf]);
                    ldsm4(KL + off, bL[hf]);
                }
            }
#pragma unroll
            for (int hf = 0; hf < 2; ++hf)
#pragma unroll
                for (int sub = 0; sub < 2; ++sub)
                    mma16816(acc[hf * 2 + sub], aH, bH[hf][sub * 2], bH[hf][sub * 2 + 1]);
#pragma unroll
            for (int hf = 0; hf < 2; ++hf)
#pragma unroll
                for (int sub = 0; sub < 2; ++sub)
                    mma16816(acc[hf * 2 + sub], aH, bL[hf][sub * 2], bL[hf][sub * 2 + 1]);
#pragma unroll
            for (int hf = 0; hf < 2; ++hf)
#pragma unroll
                for (int sub = 0; sub < 2; ++sub)
                    mma16816(acc[hf * 2 + sub], aL, bH[hf][sub * 2], bH[hf][sub * 2 + 1]);
        }
#pragma unroll
        for (int jf = 0; jf < 4; ++jf) {
            int col = kc * 64 + wn1 + jf * 8 + cq;
            float2 v0 = {acc[jf][0] * SCALE, acc[jf][1] * SCALE};
            float2 v1 = {acc[jf][2] * SCALE, acc[jf][3] * SCALE};
            *(float2*)&Sf[(fm * 16 + rq) * 256 + col]     = v0;
            *(float2*)&Sf[(fm * 16 + rq + 8) * 256 + col] = v1;
        }
    }
    __syncthreads();

    gather_kv(sb + AT_KST, g_Vh, g_Vl, sidx, 0, tid, HB);
    CP_COMMIT();

    // ---- phase 2: softmax, pack weights into Wh/Wl ----
    {
        for (int r = wid; r < 64; r += 8) {
            float vals[8], mx = -1e30f;
            float* Sr = (float*)(smc + AT_S + r * 1024);
#pragma unroll
            for (int t = 0; t < 8; ++t) {
                vals[t] = Sr[lane + t * 32];
                mx = fmaxf(mx, vals[t]);
            }
#pragma unroll
            for (int o = 16; o; o >>= 1) mx = fmaxf(mx, __shfl_xor_sync(0xffffffffu, mx, o));
            float ssum = 0.f;
#pragma unroll
            for (int t = 0; t < 8; ++t) { vals[t] = expf(vals[t] - mx); ssum += vals[t]; }
#pragma unroll
            for (int o = 16; o; o >>= 1) ssum += __shfl_xor_sync(0xffffffffu, ssum, o);
            float inv = 1.0f / ssum;
            char* rowb = smc + AT_S + r * 1024;
#pragma unroll
            for (int t = 0; t < 8; ++t) {
                float w = vals[t] * inv;
                __nv_bfloat16 hi = __float2bfloat16(w);
                __nv_bfloat16 lo = __float2bfloat16(w - __bfloat162float(hi));
                int key = lane + t * 32;
                int c = key >> 3, wi = key & 7;
                int swz = ((c ^ (r & 7)) << 4) + wi * 2;
                *(__nv_bfloat16*)(rowb + swz)       = hi;
                *(__nv_bfloat16*)(rowb + 512 + swz) = lo;
            }
        }
    }

    // ---- phase 3: O = (WhVh + WhVl + WlVh) over 4 key chunks ----
    float oacc[8][4];
#pragma unroll
    for (int i = 0; i < 8; ++i) { oacc[i][0] = oacc[i][1] = oacc[i][2] = oacc[i][3] = 0.f; }
    const int wn3 = (wid & 1) * 64;
    for (int kc = 0; kc < 4; ++kc) {
        CP_WAIT0();
        __syncthreads();
        if (kc + 1 < 4) {
            gather_kv(sb + AT_KST + ((kc + 1) & 1) * 32768, g_Vh, g_Vl, sidx, kc + 1, tid, HB);
            CP_COMMIT();
        }
        const uint32_t VH = sb + AT_KST + (kc & 1) * 32768, VL = VH + 16384;
#pragma unroll
        for (int ks = 0; ks < 4; ++ks) {
            uint32_t aH[4], aL[4];
            {
                int cg = kc * 8 + ks * 2 + (grp >> 1);
                int arow = fm * 16 + (grp & 1) * 8 + lr;
                uint32_t off = (uint32_t)(arow * 1024 + ((cg ^ (arow & 7)) << 4));
                ldsm4(sb + AT_S + off, aH);
                ldsm4(sb + AT_S + off + 512, aL);
            }
            uint32_t bH[4][4], bL[4][4];
            {
                int vrow = ks * 16 + (grp & 1) * 8 + lr;
                uint32_t rbase = (uint32_t)(vrow * 256);
                int cbase = (wn3 >> 3) + (grp >> 1);
#pragma unroll
                for (int g4 = 0; g4 < 4; ++g4) {
                    int cn = cbase + g4 * 2;
                    uint32_t off = rbase + ((cn ^ (vrow & 7)) << 4);
                    ldsm4t(VH + off, bH[g4]);
                    ldsm4t(VL + off, bL[g4]);
                }
            }
#pragma unroll
            for (int g4 = 0; g4 < 4; ++g4)
#pragma unroll
                for (int s2 = 0; s2 < 2; ++s2)
                    mma16816(oacc[g4 * 2 + s2], aH, bH[g4][s2 * 2], bH[g4][s2 * 2 + 1]);
#pragma unroll
            for (int g4 = 0; g4 < 4; ++g4)
#pragma unroll
                for (int s2 = 0; s2 < 2; ++s2)
                    mma16816(oacc[g4 * 2 + s2], aH, bL[g4][s2 * 2], bL[g4][s2 * 2 + 1]);
#pragma unroll
            for (int g4 = 0; g4 < 4; ++g4)
#pragma unroll
                for (int s2 = 0; s2 < 2; ++s2)
                    mma16816(oacc[g4 * 2 + s2], aL, bH[g4][s2 * 2], bH[g4][s2 * 2 + 1]);
        }
    }

    // epilogue: split O into Oh/Ol directly
#pragma unroll
    for (int j = 0; j < 8; ++j) {
        int col = HB + wn3 + j * 8 + cq;
        int row = n0 + fm * 16 + rq;
        float2 v0 = {oacc[j][0], oacc[j][1]};
        float2 v1 = {oacc[j][2], oacc[j][3]};
        split_store(g_Oh, g_Ol, row, col, v0);
        split_store(g_Oh, g_Ol, row + 8, col, v1);
    }
}

// ======================= host =======================
extern "C" void kernel_launch(void* const* d_in, const int* in_sizes, int n_in,
                              void* d_out, int out_size) {
    const float* X  = (const float*)d_in[0];
    const float* Wq = (const float*)d_in[1];
    const float* bq = (const float*)d_in[2];
    const float* Wk = (const float*)d_in[3];
    const float* bk = (const float*)d_in[4];
    const float* Wv = (const float*)d_in[5];
    const float* bv = (const float*)d_in[6];
    const float* Wo = (const float*)d_in[7];
    const float* bo = (const float*)d_in[8];
    float* out = (float*)d_out;

    float *Qd, *Kd;
    __nv_bfloat16 *Xh, *Xl, *Oh, *Ol, *Wh, *Wl, *Qh, *Ql, *Kh, *Kl, *Vh, *Vl;
    cudaGetSymbolAddress((void**)&Qd, g_Q);
    cudaGetSymbolAddress((void**)&Kd, g_K);
    cudaGetSymbolAddress((void**)&Xh, g_Xh);
    cudaGetSymbolAddress((void**)&Xl, g_Xl);
    cudaGetSymbolAddress((void**)&Oh, g_Oh);
    cudaGetSymbolAddress((void**)&Ol, g_Ol);
    cudaGetSymbolAddress((void**)&Wh, g_Wh);
    cudaGetSymbolAddress((void**)&Wl, g_Wl);
    cudaGetSymbolAddress((void**)&Qh, g_Qh);
    cudaGetSymbolAddress((void**)&Ql, g_Ql);
    cudaGetSymbolAddress((void**)&Kh, g_Kh);
    cudaGetSymbolAddress((void**)&Kl, g_Kl);
    cudaGetSymbolAddress((void**)&Vh, g_Vh);
    cudaGetSymbolAddress((void**)&Vl, g_Vl);

    cudaFuncSetAttribute(gemm_bf16x3, cudaFuncAttributeMaxDynamicSharedMemorySize, GSMEM);
    cudaFuncSetAttribute(attn_mma, cudaFuncAttributeMaxDynamicSharedMemorySize, ATTN_SMEM);

    const size_t WSZ = (size_t)HID * HID;

    split_f32<<<4096, 256>>>(X, Xh, Xl);
    transpose_split4<<<dim3(64, 64, 4), dim3(32, 8)>>>(Wq, Wk, Wv, Wo);

    dim3 gg(8, 16);   // 128 CTAs = single wave
    gemm_bf16x3<<<gg, 256, GSMEM>>>(Xh, Xl, Wh + 0 * WSZ, Wl + 0 * WSZ, bq, Qd, Qh, Ql);
    gemm_bf16x3<<<gg, 256, GSMEM>>>(Xh, Xl, Wh + 1 * WSZ, Wl + 1 * WSZ, bk, Kd, Kh, Kl);
    gemm_bf16x3<<<gg, 256, GSMEM>>>(Xh, Xl, Wh + 2 * WSZ, Wl + 2 * WSZ, bv, nullptr, Vh, Vl);

    colsum_part<<<dim3(8, 16), 256>>>();
    colsum_final<<<8, 256>>>();
    imp_kernel<<<4096, 256>>>();
    topk_kernel<<<64, 256>>>();

    attn_mma<<<dim3(32, 16), 256, ATTN_SMEM>>>();

    gemm_bf16x3<<<gg, 256, GSMEM>>>(Oh, Ol, Wh + 3 * WSZ, Wl + 3 * WSZ, bo, out,
                                    nullptr, nullptr);
}

// round 10
// speedup vs baseline: 1.0640x; 1.0005x over previous
#include <cuda_runtime.h>
#include <cuda_bf16.h>
#include <math.h>
#include <stdint.h>

#define HID  2048
#define NSEQ 2048
#define NH   16
#define HD   128
#define TOPK 256

// ---------------- scratch (device globals; no allocation) ----------------
__device__ float g_Q[NSEQ * HID];
__device__ float g_K[NSEQ * HID];
__device__ float g_part[16 * HID];
__device__ float g_qbar[HID];
__device__ float g_imp[NH * NSEQ];
__device__ int   g_idx[NH * TOPK];
__device__ int   g_cnt[NH];

__device__ __align__(16) __nv_bfloat16 g_Xh[NSEQ * HID];
__device__ __align__(16) __nv_bfloat16 g_Xl[NSEQ * HID];
__device__ __align__(16) __nv_bfloat16 g_Oh[NSEQ * HID];
__device__ __align__(16) __nv_bfloat16 g_Ol[NSEQ * HID];
__device__ __align__(16) __nv_bfloat16 g_Qh[NSEQ * HID];
__device__ __align__(16) __nv_bfloat16 g_Ql[NSEQ * HID];
__device__ __align__(16) __nv_bfloat16 g_Kh[NSEQ * HID];
__device__ __align__(16) __nv_bfloat16 g_Kl[NSEQ * HID];
__device__ __align__(16) __nv_bfloat16 g_Vh[NSEQ * HID];
__device__ __align__(16) __nv_bfloat16 g_Vl[NSEQ * HID];
__device__ __align__(16) __nv_bfloat16 g_Wh[4][HID * HID];   // W^T splits, [N][K]
__device__ __align__(16) __nv_bfloat16 g_Wl[4][HID * HID];

// ======================= PTX helpers (plain sm_103-safe) =======================
__device__ __forceinline__ void ldsm4(uint32_t addr, uint32_t* r) {
    asm volatile("ldmatrix.sync.aligned.m8n8.x4.shared.b16 {%0,%1,%2,%3}, [%4];"
                 : "=r"(r[0]), "=r"(r[1]), "=r"(r[2]), "=r"(r[3]) : "r"(addr));
}
__device__ __forceinline__ void ldsm4t(uint32_t addr, uint32_t* r) {
    asm volatile("ldmatrix.sync.aligned.m8n8.x4.trans.shared.b16 {%0,%1,%2,%3}, [%4];"
                 : "=r"(r[0]), "=r"(r[1]), "=r"(r[2]), "=r"(r[3]) : "r"(addr));
}
__device__ __forceinline__ void mma16816(float* d, const uint32_t* a, uint32_t b0, uint32_t b1) {
    asm volatile("mma.sync.aligned.m16n8k16.row.col.f32.bf16.bf16.f32 "
                 "{%0,%1,%2,%3}, {%4,%5,%6,%7}, {%8,%9}, {%0,%1,%2,%3};"
                 : "+f"(d[0]), "+f"(d[1]), "+f"(d[2]), "+f"(d[3])
                 : "r"(a[0]), "r"(a[1]), "r"(a[2]), "r"(a[3]), "r"(b0), "r"(b1));
}
#define CP16(dst, src) \
    asm volatile("cp.async.cg.shared.global [%0], [%1], 16;" :: "r"(dst), "l"(src))
#define CP_COMMIT() asm volatile("cp.async.commit_group;" ::: "memory")
#define CP_WAIT1()  asm volatile("cp.async.wait_group 1;" ::: "memory")
#define CP_WAIT0()  asm volatile("cp.async.wait_group 0;" ::: "memory")

__device__ __forceinline__ void split_store(__nv_bfloat16* Ch, __nv_bfloat16* Cl,
                                            int row, int col, float2 v) {
    __nv_bfloat16 h0 = __float2bfloat16(v.x), h1 = __float2bfloat16(v.y);
    uint32_t hw = (uint32_t)__bfloat16_as_ushort(h0) |
                  ((uint32_t)__bfloat16_as_ushort(h1) << 16);
    __nv_bfloat16 l0 = __float2bfloat16(v.x - __bfloat162float(h0));
    __nv_bfloat16 l1 = __float2bfloat16(v.y - __bfloat162float(h1));
    uint32_t lw = (uint32_t)__bfloat16_as_ushort(l0) |
                  ((uint32_t)__bfloat16_as_ushort(l1) << 16);
    *(uint32_t*)&Ch[(size_t)row * HID + col] = hw;
    *(uint32_t*)&Cl[(size_t)row * HID + col] = lw;
}

// ======================= split / transpose-split =======================
__global__ void split_f32(const float* __restrict__ x,
                          __nv_bfloat16* __restrict__ hi, __nv_bfloat16* __restrict__ lo) {
    int i = (blockIdx.x * 256 + threadIdx.x) * 4;
    float4 v = *(const float4*)(x + i);
    __nv_bfloat16 h0 = __float2bfloat16(v.x);
    __nv_bfloat16 h1 = __float2bfloat16(v.y);
    __nv_bfloat16 h2 = __float2bfloat16(v.z);
    __nv_bfloat16 h3 = __float2bfloat16(v.w);
    ushort4 hv = {__bfloat16_as_ushort(h0), __bfloat16_as_ushort(h1),
                  __bfloat16_as_ushort(h2), __bfloat16_as_ushort(h3)};
    __nv_bfloat16 l0 = __float2bfloat16(v.x - __bfloat162float(h0));
    __nv_bfloat16 l1 = __float2bfloat16(v.y - __bfloat162float(h1));
    __nv_bfloat16 l2 = __float2bfloat16(v.z - __bfloat162float(h2));
    __nv_bfloat16 l3 = __float2bfloat16(v.w - __bfloat162float(h3));
    ushort4 lv = {__bfloat16_as_ushort(l0), __bfloat16_as_ushort(l1),
                  __bfloat16_as_ushort(l2), __bfloat16_as_ushort(l3)};
    *(ushort4*)(hi + i) = hv;
    *(ushort4*)(lo + i) = lv;
}

// all 4 weights: [K][N] fp32 -> [N][K] bf16 hi/lo
__global__ void transpose_split4(const float* __restrict__ W0, const float* __restrict__ W1,
                                 const float* __restrict__ W2, const float* __restrict__ W3) {
    __shared__ float t[32][33];
    const float* W = blockIdx.z == 0 ? W0 : blockIdx.z == 1 ? W1 : blockIdx.z == 2 ? W2 : W3;
    __nv_bfloat16* Th = g_Wh[blockIdx.z];
    __nv_bfloat16* Tl = g_Wl[blockIdx.z];
    int n0 = blockIdx.x * 32, k0 = blockIdx.y * 32;
    int tx = threadIdx.x, ty = threadIdx.y;  // block (32, 8)
#pragma unroll
    for (int j = 0; j < 32; j += 8)
        t[ty + j][tx] = W[(size_t)(k0 + ty + j) * HID + n0 + tx];
    __syncthreads();
#pragma unroll
    for (int j = 0; j < 32; j += 8) {
        float v = t[tx][ty + j];
        __nv_bfloat16 h = __float2bfloat16(v);
        size_t o = (size_t)(n0 + ty + j) * HID + k0 + tx;
        Th[o] = h;
        Tl[o] = __float2bfloat16(v - __bfloat162float(h));
    }
}

// ======================= HMMA bf16x3 GEMM =======================
// C = (Ah+Al)[M,K] @ (Bh+Bl)^T ([N,K]) + bias.
// CTA 256x128 (MxN), BK=64, 512 threads / 16 warps, warp tile 64x32 (4Mx4N warp grid).
// 4 warps/SMSP, MMA:LDSM = 4:1, smem traffic below compute floor.
// Grid (16, 8) = 128 CTAs = single wave.
// Stage: Ah(32K)|Al(32K)|Bh(16K)|Bl(16K) = 96KB; 2 stages = 192KB.
#define OFF_AL 32768
#define OFF_BH 65536
#define OFF_BL 81920
#define GSTAGE 98304
#define GSMEM  (2 * GSTAGE)

__global__ __launch_bounds__(512, 1)
void gemm_bf16x3(const __nv_bfloat16* __restrict__ Ah, const __nv_bfloat16* __restrict__ Al,
                 const __nv_bfloat16* __restrict__ Bh, const __nv_bfloat16* __restrict__ Bl,
                 const float* __restrict__ bias, float* __restrict__ C,
                 __nv_bfloat16* __restrict__ Ch, __nv_bfloat16* __restrict__ Cl) {
    extern __shared__ char smem[];
    const uint32_t sb = (uint32_t)__cvta_generic_to_shared(smem);
    const int tid = threadIdx.x, lane = tid & 31, wid = tid >> 5;
    const int m0 = blockIdx.y * 256, n0 = blockIdx.x * 128;
    const int wm = (wid >> 2) * 64, wn = (wid & 3) * 32;   // warp tile 64x32

    const __nv_bfloat16* pAh = Ah + (size_t)m0 * HID;
    const __nv_bfloat16* pAl = Al + (size_t)m0 * HID;
    const __nv_bfloat16* pBh = Bh + (size_t)n0 * HID;
    const __nv_bfloat16* pBl = Bl + (size_t)n0 * HID;

    // 8 accumulators of 4 regs: [f(0..3) * 2 + jn(0..1)] covers m 64 x n 32?
    // No: n 32 = 2 jn16-groups x 2 sub8 -> need f*4 + jn*2 + sub = 16 accums? 
    // m16n8 output frag per MMA: d[f][n8tile], n8tile = jn*2+sub in 0..3 -> 16 accums.
    float d[16][4];
#pragma unroll
    for (int i = 0; i < 16; ++i) { d[i][0] = d[i][1] = d[i][2] = d[i][3] = 0.f; }

    const int grp = lane >> 3, lr = lane & 7;
    const int arow_b = wm + (grp & 1) * 8 + lr;
    const int brow_b = wn + (grp >> 1) * 8 + lr;
    const int akc_b = grp >> 1;
    const int bkc_b = grp & 1;

    auto load_stage = [&](int stage, int k0) {
        uint32_t sbase = sb + stage * GSTAGE;
#pragma unroll
        for (int j = 0; j < 4; ++j) {          // A: 2048 16B chunks per tile
            int id = tid + j * 512;
            int r = id >> 3, c = id & 7;
            uint32_t doff = (uint32_t)(r * 128 + ((c ^ (r & 7)) << 4));
            CP16(sbase + doff,          pAh + (size_t)r * HID + k0 + c * 8);
            CP16(sbase + OFF_AL + doff, pAl + (size_t)r * HID + k0 + c * 8);
        }
#pragma unroll
        for (int j = 0; j < 2; ++j) {          // B: 1024 16B chunks per tile
            int id = tid + j * 512;
            int r = id >> 3, c = id & 7;
            uint32_t doff = (uint32_t)(r * 128 + ((c ^ (r & 7)) << 4));
            CP16(sbase + OFF_BH + doff, pBh + (size_t)r * HID + k0 + c * 8);
            CP16(sbase + OFF_BL + doff, pBl + (size_t)r * HID + k0 + c * 8);
        }
        CP_COMMIT();
    };

    load_stage(0, 0);

    for (int kc = 0; kc < 32; ++kc) {
        if (kc + 1 < 32) {
            load_stage((kc + 1) & 1, (kc + 1) * 64);
            CP_WAIT1();
        } else {
            CP_WAIT0();
        }
        __syncthreads();

        const uint32_t base = sb + (kc & 1) * GSTAGE;
        const uint32_t TAh = base, TAl = base + OFF_AL;
        const uint32_t TBh = base + OFF_BH, TBl = base + OFF_BL;

#pragma unroll
        for (int ks = 0; ks < 4; ++ks) {
            const int akc8 = ks * 2 + akc_b;
            const int bkc8 = ks * 2 + bkc_b;
            uint32_t aH[4][4], bH[2][4];
#pragma unroll
            for (int f = 0; f < 4; ++f) {
                int row = arow_b + f * 16;
                ldsm4(TAh + (uint32_t)(row * 128 + ((akc8 ^ (row & 7)) << 4)), aH[f]);
            }
#pragma unroll
            for (int jn = 0; jn < 2; ++jn) {
                int row = brow_b + jn * 16;
                ldsm4(TBh + (uint32_t)(row * 128 + ((bkc8 ^ (row & 7)) << 4)), bH[jn]);
            }
            // sweep 1: Ah * Bh  (16 independent accumulators)
#pragma unroll
            for (int f = 0; f < 4; ++f)
#pragma unroll
                for (int jn = 0; jn < 2; ++jn)
#pragma unroll
                    for (int sub = 0; sub < 2; ++sub)
                        mma16816(d[f * 4 + jn * 2 + sub], aH[f],
                                 bH[jn][sub * 2], bH[jn][sub * 2 + 1]);
            // sweep 2: Al * Bh (load aL, aH stays live for sweep 3)
            {
                uint32_t aL[4][4];
#pragma unroll
                for (int f = 0; f < 4; ++f) {
                    int row = arow_b + f * 16;
                    ldsm4(TAl + (uint32_t)(row * 128 + ((akc8 ^ (row & 7)) << 4)), aL[f]);
                }
#pragma unroll
                for (int f = 0; f < 4; ++f)
#pragma unroll
                    for (int jn = 0; jn < 2; ++jn)
#pragma unroll
                        for (int sub = 0; sub < 2; ++sub)
                            mma16816(d[f * 4 + jn * 2 + sub], aL[f],
                                     bH[jn][sub * 2], bH[jn][sub * 2 + 1]);
            }
            // sweep 3: Ah * Bl (aL dead, bL reuses its space)
            {
                uint32_t bL[2][4];
#pragma unroll
                for (int jn = 0; jn < 2; ++jn) {
                    int row = brow_b + jn * 16;
                    ldsm4(TBl + (uint32_t)(row * 128 + ((bkc8 ^ (row & 7)) << 4)), bL[jn]);
                }
#pragma unroll
                for (int f = 0; f < 4; ++f)
#pragma unroll
                    for (int jn = 0; jn < 2; ++jn)
#pragma unroll
                        for (int sub = 0; sub < 2; ++sub)
                            mma16816(d[f * 4 + jn * 2 + sub], aH[f],
                                     bL[jn][sub * 2], bL[jn][sub * 2 + 1]);
            }
        }
        __syncthreads();
    }

    // epilogue: warp 64x32 = 4 m16 groups x 4 n8 tiles
    const int rq = lane >> 2, cq = (lane & 3) * 2;
#pragma unroll
    for (int j = 0; j < 4; ++j) {
        int col = n0 + wn + j * 8 + cq;
        float2 bb = *(const float2*)&bias[col];
#pragma unroll
        for (int f = 0; f < 4; ++f) {
            const float* dd = d[f * 4 + j];
            int row = m0 + wm + f * 16 + rq;
            float2 o0 = {dd[0] + bb.x, dd[1] + bb.y};
            float2 o1 = {dd[2] + bb.x, dd[3] + bb.y};
            if (C) {
                *(float2*)&C[(size_t)row * HID + col]       = o0;
                *(float2*)&C[(size_t)(row + 8) * HID + col] = o1;
            }
            if (Ch) {
                split_store(Ch, Cl, row, col, o0);
                split_store(Ch, Cl, row + 8, col, o1);
            }
        }
    }
}

// ---------------- column sum of Q (for qbar) ----------------
__global__ void colsum_part() {
    int c = blockIdx.x * 256 + threadIdx.x;
    int chunk = blockIdx.y;
    int n0 = chunk * 128;
    float s = 0.f;
#pragma unroll 8
    for (int n = 0; n < 128; ++n) s += g_Q[(n0 + n) * HID + c];
    g_part[chunk * HID + c] = s;
}

__global__ void colsum_final() {
    int c = blockIdx.x * 256 + threadIdx.x;
    float s = 0.f;
#pragma unroll
    for (int t = 0; t < 16; ++t) s += g_part[t * HID + c];
    g_qbar[c] = s;
}

// ---------------- importance[h, m] = qbar_h . k_m ----------------
__global__ void imp_kernel() {
    if (blockIdx.x == 0 && threadIdx.x < NH) g_cnt[threadIdx.x] = 0;
    int gw = (blockIdx.x * blockDim.x + threadIdx.x) >> 5;
    int lane = threadIdx.x & 31;
    int h = gw >> 11, m = gw & 2047;
    float4 kv = *(const float4*)&g_K[(size_t)m * HID + h * HD + lane * 4];
    float4 qv = *(const float4*)&g_qbar[h * HD + lane * 4];
    float s = kv.x * qv.x + kv.y * qv.y + kv.z * qv.z + kv.w * qv.w;
#pragma unroll
    for (int o = 16; o; o >>= 1) s += __shfl_xor_sync(0xffffffffu, s, o);
    if (!lane) g_imp[h * NSEQ + m] = s;
}

// ---------------- top-k by rank counting (64 blocks: 4 segments/head) ----------------
__global__ void topk_kernel() {
    __shared__ float sv[NSEQ];
    int h = blockIdx.x >> 2, seg = blockIdx.x & 3, tid = threadIdx.x;
    for (int i = tid; i < NSEQ; i += 256) sv[i] = g_imp[h * NSEQ + i];
    __syncthreads();
    const float4* p4 = (const float4*)sv;
#pragma unroll
    for (int e = 0; e < 2; ++e) {
        int m = seg * 512 + e * 256 + tid;
        float v = sv[m];
        int rank = 0;
        for (int j4 = 0; j4 < NSEQ / 4; ++j4) {
            float4 x = p4[j4];
            int jb = j4 * 4;
            rank += (x.x > v) + (x.y > v) + (x.z > v) + (x.w > v);
            rank += (x.x == v && jb + 0 < m);
            rank += (x.y == v && jb + 1 < m);
            rank += (x.z == v && jb + 2 < m);
            rank += (x.w == v && jb + 3 < m);
        }
        if (rank < TOPK) {
            int pos = atomicAdd(&g_cnt[h], 1);
            g_idx[h * TOPK + pos] = m;
        }
    }
}

// ======================= HMMA bf16x3 sparse attention =======================
#define AT_QH   0
#define AT_QL   16384
#define AT_KST  32768
#define AT_S    98304
#define AT_IDX  163840
#define ATTN_SMEM (163840 + 1024)

__device__ __forceinline__ void gather_kv(uint32_t dstStage,
                                          const __nv_bfloat16* __restrict__ Hi,
                                          const __nv_bfloat16* __restrict__ Lo,
                                          const int* sidx, int kc, int tid, int HB) {
#pragma unroll
    for (int j = 0; j < 4; ++j) {
        int id = tid + j * 256;
        int r = id >> 4, c = id & 15;
        int key = sidx[kc * 64 + r];
        uint32_t dst = dstStage + (uint32_t)(r * 256 + ((c ^ (r & 7)) << 4));
        CP16(dst,         Hi + (size_t)key * HID + HB + c * 8);
        CP16(dst + 16384, Lo + (size_t)key * HID + HB + c * 8);
    }
}

__global__ __launch_bounds__(256, 1)
void attn_mma() {
    extern __shared__ char smc[];
    const uint32_t sb = (uint32_t)__cvta_generic_to_shared(smc);
    const int tid = threadIdx.x, lane = tid & 31, wid = tid >> 5;
    const int h = blockIdx.y, n0 = blockIdx.x * 64, HB = h * HD;
    const int grp = lane >> 3, lr = lane & 7;
    const int fm = wid >> 1;
    const int rq = lane >> 2, cq = (lane & 3) * 2;
    const float SCALE = 0.08838834764831845f;

    int* sidx = (int*)(smc + AT_IDX);
    sidx[tid] = g_idx[h * TOPK + tid];
    __syncthreads();

#pragma unroll
    for (int j = 0; j < 4; ++j) {
        int id = tid + j * 256;
        int r = id >> 4, c = id & 15;
        uint32_t dst = sb + AT_QH + (uint32_t)(r * 256 + ((c ^ (r & 7)) << 4));
        CP16(dst,         g_Qh + (size_t)(n0 + r) * HID + HB + c * 8);
        CP16(dst + 16384, g_Ql + (size_t)(n0 + r) * HID + HB + c * 8);
    }
    gather_kv(sb + AT_KST, g_Kh, g_Kl, sidx, 0, tid, HB);
    CP_COMMIT();

    // ---- phase 1: S = scale * (QhKh + QhKl + QlKh)^T over 4 key chunks ----
    const int wn1 = (wid & 1) * 32;
    float* Sf = (float*)(smc + AT_S);
    for (int kc = 0; kc < 4; ++kc) {
        CP_WAIT0();
        __syncthreads();
        if (kc + 1 < 4) {
            gather_kv(sb + AT_KST + ((kc + 1) & 1) * 32768, g_Kh, g_Kl, sidx, kc + 1, tid, HB);
            CP_COMMIT();
        }
        const uint32_t KH = sb + AT_KST + (kc & 1) * 32768, KL = KH + 16384;
        const uint32_t QH = sb + AT_QH, QL = sb + AT_QL;
        float acc[4][4] = {};
        const int arow = fm * 16 + (grp & 1) * 8 + lr;
        const int brow = wn1 + (grp >> 1) * 8 + lr;
#pragma unroll
        for (int ks = 0; ks < 8; ++ks) {
            uint32_t aH[4], aL[4], bH[2][4], bL[2][4];
            {
                int ca = ks * 2 + (grp >> 1);
                uint32_t off = (uint32_t)(arow * 256 + ((ca ^ (arow & 7)) << 4));
                ldsm4(QH + off, aH);
                ldsm4(QL + off, aL);
            }
            {
                int cb = ks * 2 + (grp & 1);
#pragma unroll
                for (int hf = 0; hf < 2; ++hf) {
                    int row = brow + hf * 16;
                    uint32_t off = (uint32_t)(row * 256 + ((cb ^ (row & 7)) << 4));
                    ldsm4(KH + off, bH[hf]);
                    ldsm4(KL + off, bL[hf]);
                }
            }
#pragma unroll
            for (int hf = 0; hf < 2; ++hf)
#pragma unroll
                for (int sub = 0; sub < 2; ++sub)
                    mma16816(acc[hf * 2 + sub], aH, bH[hf][sub * 2], bH[hf][sub * 2 + 1]);
#pragma unroll
            for (int hf = 0; hf < 2; ++hf)
#pragma unroll
                for (int sub = 0; sub < 2; ++sub)
                    mma16816(acc[hf * 2 + sub], aH, bL[hf][sub * 2], bL[hf][sub * 2 + 1]);
#pragma unroll
            for (int hf = 0; hf < 2; ++hf)
#pragma unroll
                for (int sub = 0; sub < 2; ++sub)
                    mma16816(acc[hf * 2 + sub], aL, bH[hf][sub * 2], bH[hf][sub * 2 + 1]);
        }
#pragma unroll
        for (int jf = 0; jf < 4; ++jf) {
            int col = kc * 64 + wn1 + jf * 8 + cq;
            float2 v0 = {acc[jf][0] * SCALE, acc[jf][1] * SCALE};
            float2 v1 = {acc[jf][2] * SCALE, acc[jf][3] * SCALE};
            *(float2*)&Sf[(fm * 16 + rq) * 256 + col]     = v0;
            *(float2*)&Sf[(fm * 16 + rq + 8) * 256 + col] = v1;
        }
    }
    __syncthreads();

    gather_kv(sb + AT_KST, g_Vh, g_Vl, sidx, 0, tid, HB);
    CP_COMMIT();

    // ---- phase 2: softmax, pack weights into Wh/Wl ----
    {
        for (int r = wid; r < 64; r += 8) {
            float vals[8], mx = -1e30f;
            float* Sr = (float*)(smc + AT_S + r * 1024);
#pragma unroll
            for (int t = 0; t < 8; ++t) {
                vals[t] = Sr[lane + t * 32];
                mx = fmaxf(mx, vals[t]);
            }
#pragma unroll
            for (int o = 16; o; o >>= 1) mx = fmaxf(mx, __shfl_xor_sync(0xffffffffu, mx, o));
            float ssum = 0.f;
#pragma unroll
            for (int t = 0; t < 8; ++t) { vals[t] = expf(vals[t] - mx); ssum += vals[t]; }
#pragma unroll
            for (int o = 16; o; o >>= 1) ssum += __shfl_xor_sync(0xffffffffu, ssum, o);
            float inv = 1.0f / ssum;
            char* rowb = smc + AT_S + r * 1024;
#pragma unroll
            for (int t = 0; t < 8; ++t) {
                float w = vals[t] * inv;
                __nv_bfloat16 hi = __float2bfloat16(w);
                __nv_bfloat16 lo = __float2bfloat16(w - __bfloat162float(hi));
                int key = lane + t * 32;
                int c = key >> 3, wi = key & 7;
                int swz = ((c ^ (r & 7)) << 4) + wi * 2;
                *(__nv_bfloat16*)(rowb + swz)       = hi;
                *(__nv_bfloat16*)(rowb + 512 + swz) = lo;
            }
        }
    }

    // ---- phase 3: O = (WhVh + WhVl + WlVh) over 4 key chunks ----
    float oacc[8][4];
#pragma unroll
    for (int i = 0; i < 8; ++i) { oacc[i][0] = oacc[i][1] = oacc[i][2] = oacc[i][3] = 0.f; }
    const int wn3 = (wid & 1) * 64;
    for (int kc = 0; kc < 4; ++kc) {
        CP_WAIT0();
        __syncthreads();
        if (kc + 1 < 4) {
            gather_kv(sb + AT_KST + ((kc + 1) & 1) * 32768, g_Vh, g_Vl, sidx, kc + 1, tid, HB);
            CP_COMMIT();
        }
        const uint32_t VH = sb + AT_KST + (kc & 1) * 32768, VL = VH + 16384;
#pragma unroll
        for (int ks = 0; ks < 4; ++ks) {
            uint32_t aH[4], aL[4];
            {
                int cg = kc * 8 + ks * 2 + (grp >> 1);
                int arow = fm * 16 + (grp & 1) * 8 + lr;
                uint32_t off = (uint32_t)(arow * 1024 + ((cg ^ (arow & 7)) << 4));
                ldsm4(sb + AT_S + off, aH);
                ldsm4(sb + AT_S + off + 512, aL);
            }
            uint32_t bH[4][4], bL[4][4];
            {
                int vrow = ks * 16 + (grp & 1) * 8 + lr;
                uint32_t rbase = (uint32_t)(vrow * 256);
                int cbase = (wn3 >> 3) + (grp >> 1);
#pragma unroll
                for (int g4 = 0; g4 < 4; ++g4) {
                    int cn = cbase + g4 * 2;
                    uint32_t off = rbase + ((cn ^ (vrow & 7)) << 4);
                    ldsm4t(VH + off, bH[g4]);
                    ldsm4t(VL + off, bL[g4]);
                }
            }
#pragma unroll
            for (int g4 = 0; g4 < 4; ++g4)
#pragma unroll
                for (int s2 = 0; s2 < 2; ++s2)
                    mma16816(oacc[g4 * 2 + s2], aH, bH[g4][s2 * 2], bH[g4][s2 * 2 + 1]);
#pragma unroll
            for (int g4 = 0; g4 < 4; ++g4)
#pragma unroll
                for (int s2 = 0; s2 < 2; ++s2)
                    mma16816(oacc[g4 * 2 + s2], aH, bL[g4][s2 * 2], bL[g4][s2 * 2 + 1]);
#pragma unroll
            for (int g4 = 0; g4 < 4; ++g4)
#pragma unroll
                for (int s2 = 0; s2 < 2; ++s2)
                    mma16816(oacc[g4 * 2 + s2], aL, bH[g4][s2 * 2], bH[g4][s2 * 2 + 1]);
        }
    }

    // epilogue: split O into Oh/Ol directly
#pragma unroll
    for (int j = 0; j < 8; ++j) {
        int col = HB + wn3 + j * 8 + cq;
        int row = n0 + fm * 16 + rq;
        float2 v0 = {oacc[j][0], oacc[j][1]};
        float2 v1 = {oacc[j][2], oacc[j][3]};
        split_store(g_Oh, g_Ol, row, col, v0);
        split_store(g_Oh, g_Ol, row + 8, col, v1);
    }
}

// ======================= host =======================
extern "C" void kernel_launch(void* const* d_in, const int* in_sizes, int n_in,
                              void* d_out, int out_size) {
    const float* X  = (const float*)d_in[0];
    const float* Wq = (const float*)d_in[1];
    const float* bq = (const float*)d_in[2];
    const float* Wk = (const float*)d_in[3];
    const float* bk = (const float*)d_in[4];
    const float* Wv = (const float*)d_in[5];
    const float* bv = (const float*)d_in[6];
    const float* Wo = (const float*)d_in[7];
    const float* bo = (const float*)d_in[8];
    float* out = (float*)d_out;

    float *Qd, *Kd;
    __nv_bfloat16 *Xh, *Xl, *Oh, *Ol, *Wh, *Wl, *Qh, *Ql, *Kh, *Kl, *Vh, *Vl;
    cudaGetSymbolAddress((void**)&Qd, g_Q);
    cudaGetSymbolAddress((void**)&Kd, g_K);
    cudaGetSymbolAddress((void**)&Xh, g_Xh);
    cudaGetSymbolAddress((void**)&Xl, g_Xl);
    cudaGetSymbolAddress((void**)&Oh, g_Oh);
    cudaGetSymbolAddress((void**)&Ol, g_Ol);
    cudaGetSymbolAddress((void**)&Wh, g_Wh);
    cudaGetSymbolAddress((void**)&Wl, g_Wl);
    cudaGetSymbolAddress((void**)&Qh, g_Qh);
    cudaGetSymbolAddress((void**)&Ql, g_Ql);
    cudaGetSymbolAddress((void**)&Kh, g_Kh);
    cudaGetSymbolAddress((void**)&Kl, g_Kl);
    cudaGetSymbolAddress((void**)&Vh, g_Vh);
    cudaGetSymbolAddress((void**)&Vl, g_Vl);

    cudaFuncSetAttribute(gemm_bf16x3, cudaFuncAttributeMaxDynamicSharedMemorySize, GSMEM);
    cudaFuncSetAttribute(attn_mma, cudaFuncAttributeMaxDynamicSharedMemorySize, ATTN_SMEM);

    const size_t WSZ = (size_t)HID * HID;

    split_f32<<<4096, 256>>>(X, Xh, Xl);
    transpose_split4<<<dim3(64, 64, 4), dim3(32, 8)>>>(Wq, Wk, Wv, Wo);

    dim3 gg(16, 8);   // N/128 x M/256 = 128 CTAs single wave
    gemm_bf16x3<<<gg, 512, GSMEM>>>(Xh, Xl, Wh + 0 * WSZ, Wl + 0 * WSZ, bq, Qd, Qh, Ql);
    gemm_bf16x3<<<gg, 512, GSMEM>>>(Xh, Xl, Wh + 1 * WSZ, Wl + 1 * WSZ, bk, Kd, Kh, Kl);
    gemm_bf16x3<<<gg, 512, GSMEM>>>(Xh, Xl, Wh + 2 * WSZ, Wl + 2 * WSZ, bv, nullptr, Vh, Vl);

    colsum_part<<<dim3(8, 16), 256>>>();
    colsum_final<<<8, 256>>>();
    imp_kernel<<<4096, 256>>>();
    topk_kernel<<<64, 256>>>();

    attn_mma<<<dim3(32, 16), 256, ATTN_SMEM>>>();

    gemm_bf16x3<<<gg, 512, GSMEM>>>(Oh, Ol, Wh + 3 * WSZ, Wl + 3 * WSZ, bo, out,
                                    nullptr, nullptr);
}

// round 11
// speedup vs baseline: 1.1322x; 1.0641x over previous
#include <cuda_runtime.h>
#include <cuda_bf16.h>
#include <math.h>
#include <stdint.h>

#define HID  2048
#define NSEQ 2048
#define NH   16
#define HD   128
#define TOPK 256

// ---------------- scratch (device globals; no allocation) ----------------
__device__ float g_qbar[HID];
__device__ float g_imp[NH * NSEQ];
__device__ int   g_idx[NH * TOPK];
__device__ int   g_cnt[NH];

__device__ __align__(16) __nv_bfloat16 g_Xh[NSEQ * HID];
__device__ __align__(16) __nv_bfloat16 g_Xl[NSEQ * HID];
__device__ __align__(16) __nv_bfloat16 g_Oh[NSEQ * HID];
__device__ __align__(16) __nv_bfloat16 g_Ol[NSEQ * HID];
__device__ __align__(16) __nv_bfloat16 g_Qh[NSEQ * HID];
__device__ __align__(16) __nv_bfloat16 g_Ql[NSEQ * HID];
__device__ __align__(16) __nv_bfloat16 g_Kh[NSEQ * HID];
__device__ __align__(16) __nv_bfloat16 g_Kl[NSEQ * HID];
__device__ __align__(16) __nv_bfloat16 g_Vh[NSEQ * HID];
__device__ __align__(16) __nv_bfloat16 g_Vl[NSEQ * HID];
__device__ __align__(16) __nv_bfloat16 g_Wh[4][HID * HID];   // W^T splits, [N][K]
__device__ __align__(16) __nv_bfloat16 g_Wl[4][HID * HID];

// ======================= PTX helpers (plain sm_103-safe) =======================
__device__ __forceinline__ void ldsm4(uint32_t addr, uint32_t* r) {
    asm volatile("ldmatrix.sync.aligned.m8n8.x4.shared.b16 {%0,%1,%2,%3}, [%4];"
                 : "=r"(r[0]), "=r"(r[1]), "=r"(r[2]), "=r"(r[3]) : "r"(addr));
}
__device__ __forceinline__ void ldsm4t(uint32_t addr, uint32_t* r) {
    asm volatile("ldmatrix.sync.aligned.m8n8.x4.trans.shared.b16 {%0,%1,%2,%3}, [%4];"
                 : "=r"(r[0]), "=r"(r[1]), "=r"(r[2]), "=r"(r[3]) : "r"(addr));
}
__device__ __forceinline__ void mma16816(float* d, const uint32_t* a, uint32_t b0, uint32_t b1) {
    asm volatile("mma.sync.aligned.m16n8k16.row.col.f32.bf16.bf16.f32 "
                 "{%0,%1,%2,%3}, {%4,%5,%6,%7}, {%8,%9}, {%0,%1,%2,%3};"
                 : "+f"(d[0]), "+f"(d[1]), "+f"(d[2]), "+f"(d[3])
                 : "r"(a[0]), "r"(a[1]), "r"(a[2]), "r"(a[3]), "r"(b0), "r"(b1));
}
#define CP16(dst, src) \
    asm volatile("cp.async.cg.shared.global [%0], [%1], 16;" :: "r"(dst), "l"(src))
#define CP_COMMIT() asm volatile("cp.async.commit_group;" ::: "memory")
#define CP_WAIT1()  asm volatile("cp.async.wait_group 1;" ::: "memory")
#define CP_WAIT0()  asm volatile("cp.async.wait_group 0;" ::: "memory")

__device__ __forceinline__ void split_store(__nv_bfloat16* Ch, __nv_bfloat16* Cl,
                                            int row, int col, float2 v) {
    __nv_bfloat16 h0 = __float2bfloat16(v.x), h1 = __float2bfloat16(v.y);
    uint32_t hw = (uint32_t)__bfloat16_as_ushort(h0) |
                  ((uint32_t)__bfloat16_as_ushort(h1) << 16);
    __nv_bfloat16 l0 = __float2bfloat16(v.x - __bfloat162float(h0));
    __nv_bfloat16 l1 = __float2bfloat16(v.y - __bfloat162float(h1));
    uint32_t lw = (uint32_t)__bfloat16_as_ushort(l0) |
                  ((uint32_t)__bfloat16_as_ushort(l1) << 16);
    *(uint32_t*)&Ch[(size_t)row * HID + col] = hw;
    *(uint32_t*)&Cl[(size_t)row * HID + col] = lw;
}

// ======================= split / transpose-split =======================
__global__ void split_f32(const float* __restrict__ x,
                          __nv_bfloat16* __restrict__ hi, __nv_bfloat16* __restrict__ lo) {
    int i = (blockIdx.x * 256 + threadIdx.x) * 4;
    float4 v = *(const float4*)(x + i);
    __nv_bfloat16 h0 = __float2bfloat16(v.x);
    __nv_bfloat16 h1 = __float2bfloat16(v.y);
    __nv_bfloat16 h2 = __float2bfloat16(v.z);
    __nv_bfloat16 h3 = __float2bfloat16(v.w);
    ushort4 hv = {__bfloat16_as_ushort(h0), __bfloat16_as_ushort(h1),
                  __bfloat16_as_ushort(h2), __bfloat16_as_ushort(h3)};
    __nv_bfloat16 l0 = __float2bfloat16(v.x - __bfloat162float(h0));
    __nv_bfloat16 l1 = __float2bfloat16(v.y - __bfloat162float(h1));
    __nv_bfloat16 l2 = __float2bfloat16(v.z - __bfloat162float(h2));
    __nv_bfloat16 l3 = __float2bfloat16(v.w - __bfloat162float(h3));
    ushort4 lv = {__bfloat16_as_ushort(l0), __bfloat16_as_ushort(l1),
                  __bfloat16_as_ushort(l2), __bfloat16_as_ushort(l3)};
    *(ushort4*)(hi + i) = hv;
    *(ushort4*)(lo + i) = lv;
}

__global__ void zero_qbar() {
    g_qbar[blockIdx.x * 256 + threadIdx.x] = 0.f;
}

// all 4 weights: [K][N] fp32 -> [N][K] bf16 hi/lo
__global__ void transpose_split4(const float* __restrict__ W0, const float* __restrict__ W1,
                                 const float* __restrict__ W2, const float* __restrict__ W3) {
    __shared__ float t[32][33];
    const float* W = blockIdx.z == 0 ? W0 : blockIdx.z == 1 ? W1 : blockIdx.z == 2 ? W2 : W3;
    __nv_bfloat16* Th = g_Wh[blockIdx.z];
    __nv_bfloat16* Tl = g_Wl[blockIdx.z];
    int n0 = blockIdx.x * 32, k0 = blockIdx.y * 32;
    int tx = threadIdx.x, ty = threadIdx.y;  // block (32, 8)
#pragma unroll
    for (int j = 0; j < 32; j += 8)
        t[ty + j][tx] = W[(size_t)(k0 + ty + j) * HID + n0 + tx];
    __syncthreads();
#pragma unroll
    for (int j = 0; j < 32; j += 8) {
        float v = t[tx][ty + j];
        __nv_bfloat16 h = __float2bfloat16(v);
        size_t o = (size_t)(n0 + ty + j) * HID + k0 + tx;
        Th[o] = h;
        Tl[o] = __float2bfloat16(v - __bfloat162float(h));
    }
}

// ======================= HMMA bf16x3 GEMM =======================
// C = (Ah+Al)[M,K] @ (Bh+Bl)^T ([N,K]) + bias.
// CTA 256x128 (MxN), BK=64, 512 threads / 16 warps, warp tile 64x32.
// Grid (16, 8) = 128 CTAs = single wave. qsum != nullptr: fused column-sum (qbar).
#define OFF_AL 32768
#define OFF_BH 65536
#define OFF_BL 81920
#define GSTAGE 98304
#define GSMEM  (2 * GSTAGE)

__global__ __launch_bounds__(512, 1)
void gemm_bf16x3(const __nv_bfloat16* __restrict__ Ah, const __nv_bfloat16* __restrict__ Al,
                 const __nv_bfloat16* __restrict__ Bh, const __nv_bfloat16* __restrict__ Bl,
                 const float* __restrict__ bias, float* __restrict__ C,
                 __nv_bfloat16* __restrict__ Ch, __nv_bfloat16* __restrict__ Cl,
                 float* __restrict__ qsum) {
    extern __shared__ char smem[];
    const uint32_t sb = (uint32_t)__cvta_generic_to_shared(smem);
    const int tid = threadIdx.x, lane = tid & 31, wid = tid >> 5;
    const int m0 = blockIdx.y * 256, n0 = blockIdx.x * 128;
    const int wm = (wid >> 2) * 64, wn = (wid & 3) * 32;

    const __nv_bfloat16* pAh = Ah + (size_t)m0 * HID;
    const __nv_bfloat16* pAl = Al + (size_t)m0 * HID;
    const __nv_bfloat16* pBh = Bh + (size_t)n0 * HID;
    const __nv_bfloat16* pBl = Bl + (size_t)n0 * HID;

    float d[16][4];
#pragma unroll
    for (int i = 0; i < 16; ++i) { d[i][0] = d[i][1] = d[i][2] = d[i][3] = 0.f; }

    const int grp = lane >> 3, lr = lane & 7;
    const int arow_b = wm + (grp & 1) * 8 + lr;
    const int brow_b = wn + (grp >> 1) * 8 + lr;
    const int akc_b = grp >> 1;
    const int bkc_b = grp & 1;

    auto load_stage = [&](int stage, int k0) {
        uint32_t sbase = sb + stage * GSTAGE;
#pragma unroll
        for (int j = 0; j < 4; ++j) {
            int id = tid + j * 512;
            int r = id >> 3, c = id & 7;
            uint32_t doff = (uint32_t)(r * 128 + ((c ^ (r & 7)) << 4));
            CP16(sbase + doff,          pAh + (size_t)r * HID + k0 + c * 8);
            CP16(sbase + OFF_AL + doff, pAl + (size_t)r * HID + k0 + c * 8);
        }
#pragma unroll
        for (int j = 0; j < 2; ++j) {
            int id = tid + j * 512;
            int r = id >> 3, c = id & 7;
            uint32_t doff = (uint32_t)(r * 128 + ((c ^ (r & 7)) << 4));
            CP16(sbase + OFF_BH + doff, pBh + (size_t)r * HID + k0 + c * 8);
            CP16(sbase + OFF_BL + doff, pBl + (size_t)r * HID + k0 + c * 8);
        }
        CP_COMMIT();
    };

    load_stage(0, 0);

    for (int kc = 0; kc < 32; ++kc) {
        if (kc + 1 < 32) {
            load_stage((kc + 1) & 1, (kc + 1) * 64);
            CP_WAIT1();
        } else {
            CP_WAIT0();
        }
        __syncthreads();

        const uint32_t base = sb + (kc & 1) * GSTAGE;
        const uint32_t TAh = base, TAl = base + OFF_AL;
        const uint32_t TBh = base + OFF_BH, TBl = base + OFF_BL;

#pragma unroll
        for (int ks = 0; ks < 4; ++ks) {
            const int akc8 = ks * 2 + akc_b;
            const int bkc8 = ks * 2 + bkc_b;
            uint32_t aH[4][4], bH[2][4];
#pragma unroll
            for (int f = 0; f < 4; ++f) {
                int row = arow_b + f * 16;
                ldsm4(TAh + (uint32_t)(row * 128 + ((akc8 ^ (row & 7)) << 4)), aH[f]);
            }
#pragma unroll
            for (int jn = 0; jn < 2; ++jn) {
                int row = brow_b + jn * 16;
                ldsm4(TBh + (uint32_t)(row * 128 + ((bkc8 ^ (row & 7)) << 4)), bH[jn]);
            }
            // sweep 1: Ah * Bh
#pragma unroll
            for (int f = 0; f < 4; ++f)
#pragma unroll
                for (int jn = 0; jn < 2; ++jn)
#pragma unroll
                    for (int sub = 0; sub < 2; ++sub)
                        mma16816(d[f * 4 + jn * 2 + sub], aH[f],
                                 bH[jn][sub * 2], bH[jn][sub * 2 + 1]);
            // sweep 2: Al * Bh
            {
                uint32_t aL[4][4];
#pragma unroll
                for (int f = 0; f < 4; ++f) {
                    int row = arow_b + f * 16;
                    ldsm4(TAl + (uint32_t)(row * 128 + ((akc8 ^ (row & 7)) << 4)), aL[f]);
                }
#pragma unroll
                for (int f = 0; f < 4; ++f)
#pragma unroll
                    for (int jn = 0; jn < 2; ++jn)
#pragma unroll
                        for (int sub = 0; sub < 2; ++sub)
                            mma16816(d[f * 4 + jn * 2 + sub], aL[f],
                                     bH[jn][sub * 2], bH[jn][sub * 2 + 1]);
            }
            // sweep 3: Ah * Bl
            {
                uint32_t bL[2][4];
#pragma unroll
                for (int jn = 0; jn < 2; ++jn) {
                    int row = brow_b + jn * 16;
                    ldsm4(TBl + (uint32_t)(row * 128 + ((bkc8 ^ (row & 7)) << 4)), bL[jn]);
                }
#pragma unroll
                for (int f = 0; f < 4; ++f)
#pragma unroll
                    for (int jn = 0; jn < 2; ++jn)
#pragma unroll
                        for (int sub = 0; sub < 2; ++sub)
                            mma16816(d[f * 4 + jn * 2 + sub], aH[f],
                                     bL[jn][sub * 2], bL[jn][sub * 2 + 1]);
            }
        }
        __syncthreads();
    }

    // epilogue: warp 64x32 = 4 m16 groups x 4 n8 tiles
    const int rq = lane >> 2, cq = (lane & 3) * 2;
#pragma unroll
    for (int j = 0; j < 4; ++j) {
        int col = n0 + wn + j * 8 + cq;
        float2 bb = *(const float2*)&bias[col];
        float2 cs = {0.f, 0.f};          // column sum for fused qbar
#pragma unroll
        for (int f = 0; f < 4; ++f) {
            const float* dd = d[f * 4 + j];
            int row = m0 + wm + f * 16 + rq;
            float2 o0 = {dd[0] + bb.x, dd[1] + bb.y};
            float2 o1 = {dd[2] + bb.x, dd[3] + bb.y};
            if (C) {
                *(float2*)&C[(size_t)row * HID + col]       = o0;
                *(float2*)&C[(size_t)(row + 8) * HID + col] = o1;
            }
            if (Ch) {
                split_store(Ch, Cl, row, col, o0);
                split_store(Ch, Cl, row + 8, col, o1);
            }
            cs.x += o0.x + o1.x;
            cs.y += o0.y + o1.y;
        }
        if (qsum) {
            // reduce over rq lanes (stride-4 lane groups share the same columns)
#pragma unroll
            for (int o = 16; o >= 4; o >>= 1) {
                cs.x += __shfl_xor_sync(0xffffffffu, cs.x, o);
                cs.y += __shfl_xor_sync(0xffffffffu, cs.y, o);
            }
            if (rq == 0) {
                atomicAdd(&qsum[col], cs.x);
                atomicAdd(&qsum[col + 1], cs.y);
            }
        }
    }
}

// ---------------- importance[h, m] = qbar_h . (kh+kl)_m ----------------
__global__ void imp_kernel() {
    if (blockIdx.x == 0 && threadIdx.x < NH) g_cnt[threadIdx.x] = 0;
    int gw = (blockIdx.x * blockDim.x + threadIdx.x) >> 5;
    int lane = threadIdx.x & 31;
    int h = gw >> 11, m = gw & 2047;
    size_t off = (size_t)m * HID + h * HD + lane * 4;
    uint2 ah = *(const uint2*)(g_Kh + off);
    uint2 al = *(const uint2*)(g_Kl + off);
    float4 qv = *(const float4*)&g_qbar[h * HD + lane * 4];
    __nv_bfloat162 h01 = *(__nv_bfloat162*)&ah.x;
    __nv_bfloat162 h23 = *(__nv_bfloat162*)&ah.y;
    __nv_bfloat162 l01 = *(__nv_bfloat162*)&al.x;
    __nv_bfloat162 l23 = *(__nv_bfloat162*)&al.y;
    float k0 = __low2float(h01) + __low2float(l01);
    float k1 = __high2float(h01) + __high2float(l01);
    float k2 = __low2float(h23) + __low2float(l23);
    float k3 = __high2float(h23) + __high2float(l23);
    float s = k0 * qv.x + k1 * qv.y + k2 * qv.z + k3 * qv.w;
#pragma unroll
    for (int o = 16; o; o >>= 1) s += __shfl_xor_sync(0xffffffffu, s, o);
    if (!lane) g_imp[h * NSEQ + m] = s;
}

// ---------------- top-k by rank counting (128 blocks: 8 segments/head) ----------------
__global__ void topk_kernel() {
    __shared__ float sv[NSEQ];
    int h = blockIdx.x >> 3, seg = blockIdx.x & 7, tid = threadIdx.x;
    for (int i = tid; i < NSEQ; i += 256) sv[i] = g_imp[h * NSEQ + i];
    __syncthreads();
    const float4* p4 = (const float4*)sv;
    int m = seg * 256 + tid;
    float v = sv[m];
    int rank = 0;
    for (int j4 = 0; j4 < NSEQ / 4; ++j4) {
        float4 x = p4[j4];
        int jb = j4 * 4;
        rank += (x.x > v) + (x.y > v) + (x.z > v) + (x.w > v);
        rank += (x.x == v && jb + 0 < m);
        rank += (x.y == v && jb + 1 < m);
        rank += (x.z == v && jb + 2 < m);
        rank += (x.w == v && jb + 3 < m);
    }
    if (rank < TOPK) {
        int pos = atomicAdd(&g_cnt[h], 1);
        g_idx[h * TOPK + pos] = m;
    }
}

// ======================= HMMA bf16x3 sparse attention =======================
#define AT_QH   0
#define AT_QL   16384
#define AT_KST  32768
#define AT_S    98304
#define AT_IDX  163840
#define ATTN_SMEM (163840 + 1024)

__device__ __forceinline__ void gather_kv(uint32_t dstStage,
                                          const __nv_bfloat16* __restrict__ Hi,
                                          const __nv_bfloat16* __restrict__ Lo,
                                          const int* sidx, int kc, int tid, int HB) {
#pragma unroll
    for (int j = 0; j < 4; ++j) {
        int id = tid + j * 256;
        int r = id >> 4, c = id & 15;
        int key = sidx[kc * 64 + r];
        uint32_t dst = dstStage + (uint32_t)(r * 256 + ((c ^ (r & 7)) << 4));
        CP16(dst,         Hi + (size_t)key * HID + HB + c * 8);
        CP16(dst + 16384, Lo + (size_t)key * HID + HB + c * 8);
    }
}

__global__ __launch_bounds__(256, 1)
void attn_mma() {
    extern __shared__ char smc[];
    const uint32_t sb = (uint32_t)__cvta_generic_to_shared(smc);
    const int tid = threadIdx.x, lane = tid & 31, wid = tid >> 5;
    const int h = blockIdx.y, n0 = blockIdx.x * 64, HB = h * HD;
    const int grp = lane >> 3, lr = lane & 7;
    const int fm = wid >> 1;
    const int rq = lane >> 2, cq = (lane & 3) * 2;
    const float SCALE = 0.08838834764831845f;

    int* sidx = (int*)(smc + AT_IDX);
    sidx[tid] = g_idx[h * TOPK + tid];
    __syncthreads();

#pragma unroll
    for (int j = 0; j < 4; ++j) {
        int id = tid + j * 256;
        int r = id >> 4, c = id & 15;
        uint32_t dst = sb + AT_QH + (uint32_t)(r * 256 + ((c ^ (r & 7)) << 4));
        CP16(dst,         g_Qh + (size_t)(n0 + r) * HID + HB + c * 8);
        CP16(dst + 16384, g_Ql + (size_t)(n0 + r) * HID + HB + c * 8);
    }
    gather_kv(sb + AT_KST, g_Kh, g_Kl, sidx, 0, tid, HB);
    CP_COMMIT();

    // ---- phase 1: S = scale * (QhKh + QhKl + QlKh)^T over 4 key chunks ----
    const int wn1 = (wid & 1) * 32;
    float* Sf = (float*)(smc + AT_S);
    for (int kc = 0; kc < 4; ++kc) {
        CP_WAIT0();
        __syncthreads();
        if (kc + 1 < 4) {
            gather_kv(sb + AT_KST + ((kc + 1) & 1) * 32768, g_Kh, g_Kl, sidx, kc + 1, tid, HB);
            CP_COMMIT();
        }
        const uint32_t KH = sb + AT_KST + (kc & 1) * 32768, KL = KH + 16384;
        const uint32_t QH = sb + AT_QH, QL = sb + AT_QL;
        float acc[4][4] = {};
        const int arow = fm * 16 + (grp & 1) * 8 + lr;
        const int brow = wn1 + (grp >> 1) * 8 + lr;
#pragma unroll
        for (int ks = 0; ks < 8; ++ks) {
            uint32_t aH[4], aL[4], bH[2][4], bL[2][4];
            {
                int ca = ks * 2 + (grp >> 1);
                uint32_t off = (uint32_t)(arow * 256 + ((ca ^ (arow & 7)) << 4));
                ldsm4(QH + off, aH);
                ldsm4(QL + off, aL);
            }
            {
                int cb = ks * 2 + (grp & 1);
#pragma unroll
                for (int hf = 0; hf < 2; ++hf) {
                    int row = brow + hf * 16;
                    uint32_t off = (uint32_t)(row * 256 + ((cb ^ (row & 7)) << 4));
                    ldsm4(KH + off, bH[hf]);
                    ldsm4(KL + off, bL[hf]);
                }
            }
#pragma unroll
            for (int hf = 0; hf < 2; ++hf)
#pragma unroll
                for (int sub = 0; sub < 2; ++sub)
                    mma16816(acc[hf * 2 + sub], aH, bH[hf][sub * 2], bH[hf][sub * 2 + 1]);
#pragma unroll
            for (int hf = 0; hf < 2; ++hf)
#pragma unroll
                for (int sub = 0; sub < 2; ++sub)
                    mma16816(acc[hf * 2 + sub], aH, bL[hf][sub * 2], bL[hf][sub * 2 + 1]);
#pragma unroll
            for (int hf = 0; hf < 2; ++hf)
#pragma unroll
                for (int sub = 0; sub < 2; ++sub)
                    mma16816(acc[hf * 2 + sub], aL, bH[hf][sub * 2], bH[hf][sub * 2 + 1]);
        }
#pragma unroll
        for (int jf = 0; jf < 4; ++jf) {
            int col = kc * 64 + wn1 + jf * 8 + cq;
            float2 v0 = {acc[jf][0] * SCALE, acc[jf][1] * SCALE};
            float2 v1 = {acc[jf][2] * SCALE, acc[jf][3] * SCALE};
            *(float2*)&Sf[(fm * 16 + rq) * 256 + col]     = v0;
            *(float2*)&Sf[(fm * 16 + rq + 8) * 256 + col] = v1;
        }
    }
    __syncthreads();

    gather_kv(sb + AT_KST, g_Vh, g_Vl, sidx, 0, tid, HB);
    CP_COMMIT();

    // ---- phase 2: softmax, pack weights into Wh/Wl ----
    {
        for (int r = wid; r < 64; r += 8) {
            float vals[8], mx = -1e30f;
            float* Sr = (float*)(smc + AT_S + r * 1024);
#pragma unroll
            for (int t = 0; t < 8; ++t) {
                vals[t] = Sr[lane + t * 32];
                mx = fmaxf(mx, vals[t]);
            }
#pragma unroll
            for (int o = 16; o; o >>= 1) mx = fmaxf(mx, __shfl_xor_sync(0xffffffffu, mx, o));
            float ssum = 0.f;
#pragma unroll
            for (int t = 0; t < 8; ++t) { vals[t] = expf(vals[t] - mx); ssum += vals[t]; }
#pragma unroll
            for (int o = 16; o; o >>= 1) ssum += __shfl_xor_sync(0xffffffffu, ssum, o);
            float inv = 1.0f / ssum;
            char* rowb = smc + AT_S + r * 1024;
#pragma unroll
            for (int t = 0; t < 8; ++t) {
                float w = vals[t] * inv;
                __nv_bfloat16 hi = __float2bfloat16(w);
                __nv_bfloat16 lo = __float2bfloat16(w - __bfloat162float(hi));
                int key = lane + t * 32;
                int c = key >> 3, wi = key & 7;
                int swz = ((c ^ (r & 7)) << 4) + wi * 2;
                *(__nv_bfloat16*)(rowb + swz)       = hi;
                *(__nv_bfloat16*)(rowb + 512 + swz) = lo;
            }
        }
    }

    // ---- phase 3: O = (WhVh + WhVl + WlVh) over 4 key chunks ----
    float oacc[8][4];
#pragma unroll
    for (int i = 0; i < 8; ++i) { oacc[i][0] = oacc[i][1] = oacc[i][2] = oacc[i][3] = 0.f; }
    const int wn3 = (wid & 1) * 64;
    for (int kc = 0; kc < 4; ++kc) {
        CP_WAIT0();
        __syncthreads();
        if (kc + 1 < 4) {
            gather_kv(sb + AT_KST + ((kc + 1) & 1) * 32768, g_Vh, g_Vl, sidx, kc + 1, tid, HB);
            CP_COMMIT();
        }
        const uint32_t VH = sb + AT_KST + (kc & 1) * 32768, VL = VH + 16384;
#pragma unroll
        for (int ks = 0; ks < 4; ++ks) {
            uint32_t aH[4], aL[4];
            {
                int cg = kc * 8 + ks * 2 + (grp >> 1);
                int arow = fm * 16 + (grp & 1) * 8 + lr;
                uint32_t off = (uint32_t)(arow * 1024 + ((cg ^ (arow & 7)) << 4));
                ldsm4(sb + AT_S + off, aH);
                ldsm4(sb + AT_S + off + 512, aL);
            }
            uint32_t bH[4][4], bL[4][4];
            {
                int vrow = ks * 16 + (grp & 1) * 8 + lr;
                uint32_t rbase = (uint32_t)(vrow * 256);
                int cbase = (wn3 >> 3) + (grp >> 1);
#pragma unroll
                for (int g4 = 0; g4 < 4; ++g4) {
                    int cn = cbase + g4 * 2;
                    uint32_t off = rbase + ((cn ^ (vrow & 7)) << 4);
                    ldsm4t(VH + off, bH[g4]);
                    ldsm4t(VL + off, bL[g4]);
                }
            }
#pragma unroll
            for (int g4 = 0; g4 < 4; ++g4)
#pragma unroll
                for (int s2 = 0; s2 < 2; ++s2)
                    mma16816(oacc[g4 * 2 + s2], aH, bH[g4][s2 * 2], bH[g4][s2 * 2 + 1]);
#pragma unroll
            for (int g4 = 0; g4 < 4; ++g4)
#pragma unroll
                for (int s2 = 0; s2 < 2; ++s2)
                    mma16816(oacc[g4 * 2 + s2], aH, bL[g4][s2 * 2], bL[g4][s2 * 2 + 1]);
#pragma unroll
            for (int g4 = 0; g4 < 4; ++g4)
#pragma unroll
                for (int s2 = 0; s2 < 2; ++s2)
                    mma16816(oacc[g4 * 2 + s2], aL, bH[g4][s2 * 2], bH[g4][s2 * 2 + 1]);
        }
    }

    // epilogue: split O into Oh/Ol directly
#pragma unroll
    for (int j = 0; j < 8; ++j) {
        int col = HB + wn3 + j * 8 + cq;
        int row = n0 + fm * 16 + rq;
        float2 v0 = {oacc[j][0], oacc[j][1]};
        float2 v1 = {oacc[j][2], oacc[j][3]};
        split_store(g_Oh, g_Ol, row, col, v0);
        split_store(g_Oh, g_Ol, row + 8, col, v1);
    }
}

// ======================= host =======================
extern "C" void kernel_launch(void* const* d_in, const int* in_sizes, int n_in,
                              void* d_out, int out_size) {
    const float* X  = (const float*)d_in[0];
    const float* Wq = (const float*)d_in[1];
    const float* bq = (const float*)d_in[2];
    const float* Wk = (const float*)d_in[3];
    const float* bk = (const float*)d_in[4];
    const float* Wv = (const float*)d_in[5];
    const float* bv = (const float*)d_in[6];
    const float* Wo = (const float*)d_in[7];
    const float* bo = (const float*)d_in[8];
    float* out = (float*)d_out;

    float* qbar;
    __nv_bfloat16 *Xh, *Xl, *Oh, *Ol, *Wh, *Wl, *Qh, *Ql, *Kh, *Kl, *Vh, *Vl;
    cudaGetSymbolAddress((void**)&qbar, g_qbar);
    cudaGetSymbolAddress((void**)&Xh, g_Xh);
    cudaGetSymbolAddress((void**)&Xl, g_Xl);
    cudaGetSymbolAddress((void**)&Oh, g_Oh);
    cudaGetSymbolAddress((void**)&Ol, g_Ol);
    cudaGetSymbolAddress((void**)&Wh, g_Wh);
    cudaGetSymbolAddress((void**)&Wl, g_Wl);
    cudaGetSymbolAddress((void**)&Qh, g_Qh);
    cudaGetSymbolAddress((void**)&Ql, g_Ql);
    cudaGetSymbolAddress((void**)&Kh, g_Kh);
    cudaGetSymbolAddress((void**)&Kl, g_Kl);
    cudaGetSymbolAddress((void**)&Vh, g_Vh);
    cudaGetSymbolAddress((void**)&Vl, g_Vl);

    cudaFuncSetAttribute(gemm_bf16x3, cudaFuncAttributeMaxDynamicSharedMemorySize, GSMEM);
    cudaFuncSetAttribute(attn_mma, cudaFuncAttributeMaxDynamicSharedMemorySize, ATTN_SMEM);

    // side stream + events (created once; reused every call, incl. under capture)
    static cudaStream_t s1 = nullptr;
    static cudaEvent_t ev0 = nullptr, ev1 = nullptr, ev2 = nullptr, ev3 = nullptr;
    if (!s1) {
        cudaStreamCreateWithFlags(&s1, cudaStreamNonBlocking);
        cudaEventCreateWithFlags(&ev0, cudaEventDisableTiming);
        cudaEventCreateWithFlags(&ev1, cudaEventDisableTiming);
        cudaEventCreateWithFlags(&ev2, cudaEventDisableTiming);
        cudaEventCreateWithFlags(&ev3, cudaEventDisableTiming);
    }

    const size_t WSZ = (size_t)HID * HID;
    dim3 gg(16, 8);   // 128 CTAs single wave

    // fork: weight transposes on s1, X split + qbar zero on main
    cudaEventRecord(ev0, 0);
    cudaStreamWaitEvent(s1, ev0, 0);
    transpose_split4<<<dim3(64, 64, 4), dim3(32, 8), 0, s1>>>(Wq, Wk, Wv, Wo);
    split_f32<<<4096, 256>>>(X, Xh, Xl);
    zero_qbar<<<8, 256>>>();
    cudaEventRecord(ev1, s1);
    cudaStreamWaitEvent(0, ev1, 0);

    // Q GEMM (fused qbar column sums), then K GEMM
    gemm_bf16x3<<<gg, 512, GSMEM>>>(Xh, Xl, Wh + 0 * WSZ, Wl + 0 * WSZ, bq,
                                    nullptr, Qh, Ql, qbar);
    gemm_bf16x3<<<gg, 512, GSMEM>>>(Xh, Xl, Wh + 1 * WSZ, Wl + 1 * WSZ, bk,
                                    nullptr, Kh, Kl, nullptr);

    // fork: imp + topk on s1 overlap the V GEMM on main
    cudaEventRecord(ev2, 0);
    cudaStreamWaitEvent(s1, ev2, 0);
    imp_kernel<<<4096, 256, 0, s1>>>();
    topk_kernel<<<128, 256, 0, s1>>>();
    gemm_bf16x3<<<gg, 512, GSMEM>>>(Xh, Xl, Wh + 2 * WSZ, Wl + 2 * WSZ, bv,
                                    nullptr, Vh, Vl, nullptr);
    cudaEventRecord(ev3, s1);
    cudaStreamWaitEvent(0, ev3, 0);

    attn_mma<<<dim3(32, 16), 256, ATTN_SMEM>>>();

    gemm_bf16x3<<<gg, 512, GSMEM>>>(Oh, Ol, Wh + 3 * WSZ, Wl + 3 * WSZ, bo, out,
                                    nullptr, nullptr, nullptr);
}